// round 1
// baseline (speedup 1.0000x reference)
#include <cuda_runtime.h>
#include <cuda_bf16.h>
#include <math.h>

// Problem constants
#define BATCH   2
#define SEQ     2048
#define EMB     2048
#define NHEAD   16
#define HDIM    128
#define MTOT    (BATCH*SEQ)          // 4096
#define NEG_INF (-1e30f)
#define ATT_SCALE 0.08838834764831845f  // 1/sqrt(128)

// Scratch (device globals: allocation-free)
__device__ float g_Q[MTOT*EMB];
__device__ float g_K[MTOT*EMB];
__device__ float g_V[MTOT*EMB];
__device__ float g_Y[MTOT*EMB];
__device__ float g_cos[SEQ*(HDIM/2)];
__device__ float g_sin[SEQ*(HDIM/2)];

// ---------------------------------------------------------------------------
// RoPE table: cos/sin of s * theta^(-2j/128), fp32 with proper range reduction
// ---------------------------------------------------------------------------
__global__ void rope_table_kernel(float* ct, float* st) {
    int idx = blockIdx.x * blockDim.x + threadIdx.x;
    if (idx >= SEQ * (HDIM/2)) return;
    int s = idx >> 6;
    int j = idx & 63;
    float inv = powf(10000.0f, -((float)(2*j)) / 128.0f);
    float a = (float)s * inv;
    ct[idx] = cosf(a);
    st[idx] = sinf(a);
}

// ---------------------------------------------------------------------------
// RoPE application (in-place on Q and K, layout [b, s, h, d])
// ---------------------------------------------------------------------------
__global__ void rope_kernel(float* Q, float* K, const float* __restrict__ ct,
                            const float* __restrict__ st) {
    int idx = blockIdx.x * blockDim.x + threadIdx.x;
    if (idx >= MTOT * NHEAD * (HDIM/2)) return;
    int j   = idx & 63;          // pair index within head
    int rem = idx >> 6;          // m*NHEAD + h
    int s   = (rem >> 4) & (SEQ - 1);
    float c  = ct[(s << 6) + j];
    float sn = st[(s << 6) + j];
    size_t off = ((size_t)rem << 7) + (j << 1);
    float2 q = *(float2*)(Q + off);
    float2 k = *(float2*)(K + off);
    *(float2*)(Q + off) = make_float2(q.x*c - q.y*sn, q.x*sn + q.y*c);
    *(float2*)(K + off) = make_float2(k.x*c - k.y*sn, k.x*sn + k.y*c);
}

// ---------------------------------------------------------------------------
// Tiled fp32 GEMM: C[M,N] = A[M,K] * W[K,N]  (row-major, M%128==N%128==0, K%16==0)
// 128x128 block tile, BK=16, 256 threads, 8x8 per thread (split 4+4), register prefetch
// ---------------------------------------------------------------------------
__global__ __launch_bounds__(256) void gemm128(const float* __restrict__ A,
                                               const float* __restrict__ W,
                                               float* __restrict__ C,
                                               int M, int N, int K) {
    __shared__ float As[16][132];   // transposed: As[kk][m]
    __shared__ float Ws[16][132];   // Ws[kk][n]

    const int tid = threadIdx.x;
    const int bm = blockIdx.y * 128;
    const int bn = blockIdx.x * 128;
    const int tr = tid >> 4;        // 0..15
    const int tc = tid & 15;        // 0..15

    float acc[8][8];
    #pragma unroll
    for (int i = 0; i < 8; i++)
        #pragma unroll
        for (int j = 0; j < 8; j++) acc[i][j] = 0.0f;

    float4 pa[2], pw[2];
    // prefetch tile 0
    #pragma unroll
    for (int i = 0; i < 2; i++) {
        int lin = tid + (i << 8);
        pa[i] = *(const float4*)(A + (size_t)(bm + (lin >> 2)) * K + ((lin & 3) << 2));
        pw[i] = *(const float4*)(W + (size_t)(lin >> 5) * N + bn + ((lin & 31) << 2));
    }

    for (int kb = 0; kb < K; kb += 16) {
        // stage prefetched tile into smem
        #pragma unroll
        for (int i = 0; i < 2; i++) {
            int lin = tid + (i << 8);
            int ar = lin >> 2, ac = (lin & 3) << 2;
            As[ac + 0][ar] = pa[i].x;
            As[ac + 1][ar] = pa[i].y;
            As[ac + 2][ar] = pa[i].z;
            As[ac + 3][ar] = pa[i].w;
            *(float4*)&Ws[lin >> 5][(lin & 31) << 2] = pw[i];
        }
        __syncthreads();

        // prefetch next tile (global loads overlap the FMA loop below)
        if (kb + 16 < K) {
            #pragma unroll
            for (int i = 0; i < 2; i++) {
                int lin = tid + (i << 8);
                pa[i] = *(const float4*)(A + (size_t)(bm + (lin >> 2)) * K + kb + 16 + ((lin & 3) << 2));
                pw[i] = *(const float4*)(W + (size_t)(kb + 16 + (lin >> 5)) * N + bn + ((lin & 31) << 2));
            }
        }

        #pragma unroll
        for (int kk = 0; kk < 16; kk++) {
            float4 a0 = *(float4*)&As[kk][tr << 2];
            float4 a1 = *(float4*)&As[kk][64 + (tr << 2)];
            float4 b0 = *(float4*)&Ws[kk][tc << 2];
            float4 b1 = *(float4*)&Ws[kk][64 + (tc << 2)];
            float av[8] = {a0.x, a0.y, a0.z, a0.w, a1.x, a1.y, a1.z, a1.w};
            float bv[8] = {b0.x, b0.y, b0.z, b0.w, b1.x, b1.y, b1.z, b1.w};
            #pragma unroll
            for (int i = 0; i < 8; i++)
                #pragma unroll
                for (int j = 0; j < 8; j++)
                    acc[i][j] = fmaf(av[i], bv[j], acc[i][j]);
        }
        __syncthreads();
    }

    // epilogue: rows {tr*4+i, 64+tr*4+i}, cols {tc*4+j, 64+tc*4+j}
    #pragma unroll
    for (int ih = 0; ih < 2; ih++)
        #pragma unroll
        for (int i = 0; i < 4; i++) {
            size_t row = (size_t)(bm + ih * 64 + (tr << 2) + i);
            #pragma unroll
            for (int jh = 0; jh < 2; jh++) {
                float4 v;
                v.x = acc[ih * 4 + i][jh * 4 + 0];
                v.y = acc[ih * 4 + i][jh * 4 + 1];
                v.z = acc[ih * 4 + i][jh * 4 + 2];
                v.w = acc[ih * 4 + i][jh * 4 + 3];
                *(float4*)(C + row * N + bn + jh * 64 + (tc << 2)) = v;
            }
        }
}

// ---------------------------------------------------------------------------
// Causal flash attention, fp32. Q/K/V layout [b, s, h, d]; output Y same layout.
// BQ=BK=64, D=128, 256 threads. Online softmax.
// smem: Qt[128][68] (transposed), Kt[128][68] (transposed), Vs[64][132],
//       Pt[64(kcol)][68] (S/P transposed), stats m/l/scale [64].
// ---------------------------------------------------------------------------
#define QT_OFF  0
#define KT_OFF  (128*68)
#define VS_OFF  (KT_OFF + 128*68)
#define PT_OFF  (VS_OFF + 64*132)
#define MS_OFF  (PT_OFF + 64*68)
#define LS_OFF  (MS_OFF + 64)
#define SS_OFF  (LS_OFF + 64)
#define ATTN_SMEM_FLOATS (SS_OFF + 64)
#define ATTN_SMEM_BYTES  (ATTN_SMEM_FLOATS * 4)

__global__ __launch_bounds__(256) void attn_kernel(const float* __restrict__ Q,
                                                   const float* __restrict__ K,
                                                   const float* __restrict__ V,
                                                   float* __restrict__ Y) {
    extern __shared__ float sm[];
    float* Qt = sm + QT_OFF;
    float* Kt = sm + KT_OFF;
    float* Vs = sm + VS_OFF;
    float* Pt = sm + PT_OFF;
    float* ms = sm + MS_OFF;
    float* ls = sm + LS_OFF;
    float* ss = sm + SS_OFF;

    const int tid = threadIdx.x;
    const int ty = tid >> 4;   // 0..15 -> q-row group
    const int tx = tid & 15;   // 0..15 -> col group
    const int qb = blockIdx.x;
    const int h  = blockIdx.y;
    const int b  = blockIdx.z;
    const int q0 = qb * 64;

    // load Q tile transposed: Qt[d][r]
    #pragma unroll
    for (int i = 0; i < 8; i++) {
        int lin = tid + (i << 8);         // float4 index, 2048 total
        int r  = lin >> 5;                 // 0..63
        int c4 = lin & 31;                 // 0..31
        const float* src = Q + ((size_t)(b * SEQ + q0 + r) * EMB) + h * HDIM + (c4 << 2);
        float4 qv = *(const float4*)src;
        Qt[((c4 << 2) + 0) * 68 + r] = qv.x;
        Qt[((c4 << 2) + 1) * 68 + r] = qv.y;
        Qt[((c4 << 2) + 2) * 68 + r] = qv.z;
        Qt[((c4 << 2) + 3) * 68 + r] = qv.w;
    }
    if (tid < 64) { ms[tid] = NEG_INF; ls[tid] = 0.0f; }

    float o[4][8];
    #pragma unroll
    for (int i = 0; i < 4; i++)
        #pragma unroll
        for (int j = 0; j < 8; j++) o[i][j] = 0.0f;

    __syncthreads();

    const int ktiles = qb + 1;
    for (int kt = 0; kt < ktiles; kt++) {
        const int k0 = kt * 64;
        // load K (transposed) and V tiles
        #pragma unroll
        for (int i = 0; i < 8; i++) {
            int lin = tid + (i << 8);
            int r  = lin >> 5;
            int c4 = lin & 31;
            size_t goff = ((size_t)(b * SEQ + k0 + r) * EMB) + h * HDIM + (c4 << 2);
            float4 kv = *(const float4*)(K + goff);
            Kt[((c4 << 2) + 0) * 68 + r] = kv.x;
            Kt[((c4 << 2) + 1) * 68 + r] = kv.y;
            Kt[((c4 << 2) + 2) * 68 + r] = kv.z;
            Kt[((c4 << 2) + 3) * 68 + r] = kv.w;
            float4 vv = *(const float4*)(V + goff);
            *(float4*)&Vs[r * 132 + (c4 << 2)] = vv;
        }
        __syncthreads();

        // S = Q K^T  (4 rows x 4 cols per thread)
        float sacc[4][4];
        #pragma unroll
        for (int i = 0; i < 4; i++)
            #pragma unroll
            for (int j = 0; j < 4; j++) sacc[i][j] = 0.0f;

        #pragma unroll 4
        for (int d = 0; d < 128; d++) {
            float4 qv = *(float4*)&Qt[d * 68 + (ty << 2)];
            float4 kv = *(float4*)&Kt[d * 68 + (tx << 2)];
            float qa[4] = {qv.x, qv.y, qv.z, qv.w};
            float ka[4] = {kv.x, kv.y, kv.z, kv.w};
            #pragma unroll
            for (int i = 0; i < 4; i++)
                #pragma unroll
                for (int j = 0; j < 4; j++)
                    sacc[i][j] = fmaf(qa[i], ka[j], sacc[i][j]);
        }

        // mask + write transposed Pt[c][r]
        #pragma unroll
        for (int j = 0; j < 4; j++) {
            int c = (tx << 2) + j;
            float4 pv;
            float t0 = sacc[0][j] * ATT_SCALE;
            float t1 = sacc[1][j] * ATT_SCALE;
            float t2 = sacc[2][j] * ATT_SCALE;
            float t3 = sacc[3][j] * ATT_SCALE;
            pv.x = (k0 + c > q0 + (ty << 2) + 0) ? NEG_INF : t0;
            pv.y = (k0 + c > q0 + (ty << 2) + 1) ? NEG_INF : t1;
            pv.z = (k0 + c > q0 + (ty << 2) + 2) ? NEG_INF : t2;
            pv.w = (k0 + c > q0 + (ty << 2) + 3) ? NEG_INF : t3;
            *(float4*)&Pt[c * 68 + (ty << 2)] = pv;
        }
        __syncthreads();

        // online softmax: 4 threads per q-row
        {
            int r  = tid >> 2;
            int qd = tid & 3;
            float mx = NEG_INF;
            #pragma unroll
            for (int cc = 0; cc < 16; cc++)
                mx = fmaxf(mx, Pt[(qd * 16 + cc) * 68 + r]);
            mx = fmaxf(mx, __shfl_xor_sync(0xffffffffu, mx, 1));
            mx = fmaxf(mx, __shfl_xor_sync(0xffffffffu, mx, 2));
            float m_old = ms[r];
            float m_new = fmaxf(m_old, mx);
            float sum = 0.0f;
            #pragma unroll
            for (int cc = 0; cc < 16; cc++) {
                int cidx = (qd * 16 + cc) * 68 + r;
                float p = __expf(Pt[cidx] - m_new);
                Pt[cidx] = p;
                sum += p;
            }
            sum += __shfl_xor_sync(0xffffffffu, sum, 1);
            sum += __shfl_xor_sync(0xffffffffu, sum, 2);
            if (qd == 0) {
                float sc = __expf(m_old - m_new);
                ms[r] = m_new;
                ss[r] = sc;
                ls[r] = ls[r] * sc + sum;
            }
        }
        __syncthreads();

        // rescale O, then O += P @ V
        {
            float rs[4];
            #pragma unroll
            for (int i = 0; i < 4; i++) rs[i] = ss[(ty << 2) + i];
            #pragma unroll
            for (int i = 0; i < 4; i++)
                #pragma unroll
                for (int j = 0; j < 8; j++) o[i][j] *= rs[i];

            #pragma unroll 2
            for (int kk = 0; kk < 64; kk++) {
                float4 pv = *(float4*)&Pt[kk * 68 + (ty << 2)];
                float4 v0 = *(float4*)&Vs[kk * 132 + (tx << 2)];
                float4 v1 = *(float4*)&Vs[kk * 132 + 64 + (tx << 2)];
                float pr[4] = {pv.x, pv.y, pv.z, pv.w};
                float vv[8] = {v0.x, v0.y, v0.z, v0.w, v1.x, v1.y, v1.z, v1.w};
                #pragma unroll
                for (int i = 0; i < 4; i++)
                    #pragma unroll
                    for (int j = 0; j < 8; j++)
                        o[i][j] = fmaf(pr[i], vv[j], o[i][j]);
            }
        }
        __syncthreads();
    }

    // epilogue: divide by l, write Y (layout [b, s, h, d])
    #pragma unroll
    for (int i = 0; i < 4; i++) {
        int r = (ty << 2) + i;
        float inv = 1.0f / ls[r];
        float* dst = Y + ((size_t)(b * SEQ + q0 + r) * EMB) + h * HDIM;
        float4 w0, w1;
        w0.x = o[i][0] * inv; w0.y = o[i][1] * inv; w0.z = o[i][2] * inv; w0.w = o[i][3] * inv;
        w1.x = o[i][4] * inv; w1.y = o[i][5] * inv; w1.z = o[i][6] * inv; w1.w = o[i][7] * inv;
        *(float4*)(dst + (tx << 2))      = w0;
        *(float4*)(dst + 64 + (tx << 2)) = w1;
    }
}

// ---------------------------------------------------------------------------
// Launch
// ---------------------------------------------------------------------------
extern "C" void kernel_launch(void* const* d_in, const int* in_sizes, int n_in,
                              void* d_out, int out_size) {
    const float* x  = (const float*)d_in[0];
    const float* wq = (const float*)d_in[1];
    const float* wk = (const float*)d_in[2];
    const float* wv = (const float*)d_in[3];
    const float* wo = (const float*)d_in[4];
    float* out = (float*)d_out;

    float *qp, *kp, *vp, *yp, *cp, *sp;
    cudaGetSymbolAddress((void**)&qp, g_Q);
    cudaGetSymbolAddress((void**)&kp, g_K);
    cudaGetSymbolAddress((void**)&vp, g_V);
    cudaGetSymbolAddress((void**)&yp, g_Y);
    cudaGetSymbolAddress((void**)&cp, g_cos);
    cudaGetSymbolAddress((void**)&sp, g_sin);

    // RoPE tables
    rope_table_kernel<<<(SEQ * (HDIM/2) + 255) / 256, 256>>>(cp, sp);

    // QKV projections
    dim3 gg(EMB / 128, MTOT / 128);   // (16, 32)
    gemm128<<<gg, 256>>>(x, wq, qp, MTOT, EMB, EMB);
    gemm128<<<gg, 256>>>(x, wk, kp, MTOT, EMB, EMB);
    gemm128<<<gg, 256>>>(x, wv, vp, MTOT, EMB, EMB);

    // RoPE on Q, K
    int rope_threads = MTOT * NHEAD * (HDIM/2);
    rope_kernel<<<(rope_threads + 255) / 256, 256>>>(qp, kp, cp, sp);

    // Attention
    cudaFuncSetAttribute(attn_kernel, cudaFuncAttributeMaxDynamicSharedMemorySize,
                         ATTN_SMEM_BYTES);
    dim3 ag(SEQ / 64, NHEAD, BATCH);  // (32, 16, 2)
    attn_kernel<<<ag, 256, ATTN_SMEM_BYTES>>>(qp, kp, vp, yp);

    // Output projection
    gemm128<<<gg, 256>>>(yp, wo, out, MTOT, EMB, EMB);
}

// round 2
// speedup vs baseline: 1.0005x; 1.0005x over previous
#include <cuda_runtime.h>
#include <cuda_bf16.h>
#include <math.h>

// Problem constants
#define BATCH   2
#define SEQ     2048
#define EMB     2048
#define NHEAD   16
#define HDIM    128
#define MTOT    (BATCH*SEQ)          // 4096
#define NEG_INF (-1e30f)
#define ATT_SCALE 0.08838834764831845f  // 1/sqrt(128)

// Scratch (device globals: allocation-free)
__device__ float g_Q[MTOT*EMB];
__device__ float g_K[MTOT*EMB];
__device__ float g_V[MTOT*EMB];
__device__ float g_Y[MTOT*EMB];
__device__ float g_cos[SEQ*(HDIM/2)];
__device__ float g_sin[SEQ*(HDIM/2)];

// ---------------------------------------------------------------------------
// RoPE table: cos/sin of s * theta^(-2j/128), fp32 with proper range reduction
// ---------------------------------------------------------------------------
__global__ void rope_table_kernel(float* ct, float* st) {
    int idx = blockIdx.x * blockDim.x + threadIdx.x;
    if (idx >= SEQ * (HDIM/2)) return;
    int s = idx >> 6;
    int j = idx & 63;
    float inv = powf(10000.0f, -((float)(2*j)) / 128.0f);
    float a = (float)s * inv;
    ct[idx] = cosf(a);
    st[idx] = sinf(a);
}

// ---------------------------------------------------------------------------
// RoPE application (in-place on Q and K, layout [b, s, h, d])
// ---------------------------------------------------------------------------
__global__ void rope_kernel(float* Q, float* K, const float* __restrict__ ct,
                            const float* __restrict__ st) {
    int idx = blockIdx.x * blockDim.x + threadIdx.x;
    if (idx >= MTOT * NHEAD * (HDIM/2)) return;
    int j   = idx & 63;          // pair index within head
    int rem = idx >> 6;          // m*NHEAD + h
    int s   = (rem >> 4) & (SEQ - 1);
    float c  = ct[(s << 6) + j];
    float sn = st[(s << 6) + j];
    size_t off = ((size_t)rem << 7) + (j << 1);
    float2 q = *(float2*)(Q + off);
    float2 k = *(float2*)(K + off);
    *(float2*)(Q + off) = make_float2(q.x*c - q.y*sn, q.x*sn + q.y*c);
    *(float2*)(K + off) = make_float2(k.x*c - k.y*sn, k.x*sn + k.y*c);
}

// ---------------------------------------------------------------------------
// Tiled fp32 GEMM: C[M,N] = A[M,K] * W[K,N]  (row-major, M%128==N%128==0, K%16==0)
// 128x128 block tile, BK=16, 256 threads, 8x8 per thread (split 4+4), register prefetch
// ---------------------------------------------------------------------------
__global__ __launch_bounds__(256) void gemm128(const float* __restrict__ A,
                                               const float* __restrict__ W,
                                               float* __restrict__ C,
                                               int M, int N, int K) {
    __shared__ float As[16][132];   // transposed: As[kk][m]
    __shared__ float Ws[16][132];   // Ws[kk][n]

    const int tid = threadIdx.x;
    const int bm = blockIdx.y * 128;
    const int bn = blockIdx.x * 128;
    const int tr = tid >> 4;        // 0..15
    const int tc = tid & 15;        // 0..15

    float acc[8][8];
    #pragma unroll
    for (int i = 0; i < 8; i++)
        #pragma unroll
        for (int j = 0; j < 8; j++) acc[i][j] = 0.0f;

    float4 pa[2], pw[2];
    // prefetch tile 0
    #pragma unroll
    for (int i = 0; i < 2; i++) {
        int lin = tid + (i << 8);
        pa[i] = *(const float4*)(A + (size_t)(bm + (lin >> 2)) * K + ((lin & 3) << 2));
        pw[i] = *(const float4*)(W + (size_t)(lin >> 5) * N + bn + ((lin & 31) << 2));
    }

    for (int kb = 0; kb < K; kb += 16) {
        // stage prefetched tile into smem
        #pragma unroll
        for (int i = 0; i < 2; i++) {
            int lin = tid + (i << 8);
            int ar = lin >> 2, ac = (lin & 3) << 2;
            As[ac + 0][ar] = pa[i].x;
            As[ac + 1][ar] = pa[i].y;
            As[ac + 2][ar] = pa[i].z;
            As[ac + 3][ar] = pa[i].w;
            *(float4*)&Ws[lin >> 5][(lin & 31) << 2] = pw[i];
        }
        __syncthreads();

        // prefetch next tile (global loads overlap the FMA loop below)
        if (kb + 16 < K) {
            #pragma unroll
            for (int i = 0; i < 2; i++) {
                int lin = tid + (i << 8);
                pa[i] = *(const float4*)(A + (size_t)(bm + (lin >> 2)) * K + kb + 16 + ((lin & 3) << 2));
                pw[i] = *(const float4*)(W + (size_t)(kb + 16 + (lin >> 5)) * N + bn + ((lin & 31) << 2));
            }
        }

        #pragma unroll
        for (int kk = 0; kk < 16; kk++) {
            float4 a0 = *(float4*)&As[kk][tr << 2];
            float4 a1 = *(float4*)&As[kk][64 + (tr << 2)];
            float4 b0 = *(float4*)&Ws[kk][tc << 2];
            float4 b1 = *(float4*)&Ws[kk][64 + (tc << 2)];
            float av[8] = {a0.x, a0.y, a0.z, a0.w, a1.x, a1.y, a1.z, a1.w};
            float bv[8] = {b0.x, b0.y, b0.z, b0.w, b1.x, b1.y, b1.z, b1.w};
            #pragma unroll
            for (int i = 0; i < 8; i++)
                #pragma unroll
                for (int j = 0; j < 8; j++)
                    acc[i][j] = fmaf(av[i], bv[j], acc[i][j]);
        }
        __syncthreads();
    }

    // epilogue: rows {tr*4+i, 64+tr*4+i}, cols {tc*4+j, 64+tc*4+j}
    #pragma unroll
    for (int ih = 0; ih < 2; ih++)
        #pragma unroll
        for (int i = 0; i < 4; i++) {
            size_t row = (size_t)(bm + ih * 64 + (tr << 2) + i);
            #pragma unroll
            for (int jh = 0; jh < 2; jh++) {
                float4 v;
                v.x = acc[ih * 4 + i][jh * 4 + 0];
                v.y = acc[ih * 4 + i][jh * 4 + 1];
                v.z = acc[ih * 4 + i][jh * 4 + 2];
                v.w = acc[ih * 4 + i][jh * 4 + 3];
                *(float4*)(C + row * N + bn + jh * 64 + (tc << 2)) = v;
            }
        }
}

// ---------------------------------------------------------------------------
// Causal flash attention, fp32. Q/K/V layout [b, s, h, d]; output Y same layout.
// BQ=BK=64, D=128, 256 threads. Online softmax.
// smem: Qt[128][68] (transposed), Kt[128][68] (transposed), Vs[64][132],
//       Pt[64(kcol)][68] (S/P transposed), stats m/l/scale [64].
// ---------------------------------------------------------------------------
#define QT_OFF  0
#define KT_OFF  (128*68)
#define VS_OFF  (KT_OFF + 128*68)
#define PT_OFF  (VS_OFF + 64*132)
#define MS_OFF  (PT_OFF + 64*68)
#define LS_OFF  (MS_OFF + 64)
#define SS_OFF  (LS_OFF + 64)
#define ATTN_SMEM_FLOATS (SS_OFF + 64)
#define ATTN_SMEM_BYTES  (ATTN_SMEM_FLOATS * 4)

__global__ __launch_bounds__(256) void attn_kernel(const float* __restrict__ Q,
                                                   const float* __restrict__ K,
                                                   const float* __restrict__ V,
                                                   float* __restrict__ Y) {
    extern __shared__ float sm[];
    float* Qt = sm + QT_OFF;
    float* Kt = sm + KT_OFF;
    float* Vs = sm + VS_OFF;
    float* Pt = sm + PT_OFF;
    float* ms = sm + MS_OFF;
    float* ls = sm + LS_OFF;
    float* ss = sm + SS_OFF;

    const int tid = threadIdx.x;
    const int ty = tid >> 4;   // 0..15 -> q-row group
    const int tx = tid & 15;   // 0..15 -> col group
    const int qb = blockIdx.x;
    const int h  = blockIdx.y;
    const int b  = blockIdx.z;
    const int q0 = qb * 64;

    // load Q tile transposed: Qt[d][r]
    #pragma unroll
    for (int i = 0; i < 8; i++) {
        int lin = tid + (i << 8);         // float4 index, 2048 total
        int r  = lin >> 5;                 // 0..63
        int c4 = lin & 31;                 // 0..31
        const float* src = Q + ((size_t)(b * SEQ + q0 + r) * EMB) + h * HDIM + (c4 << 2);
        float4 qv = *(const float4*)src;
        Qt[((c4 << 2) + 0) * 68 + r] = qv.x;
        Qt[((c4 << 2) + 1) * 68 + r] = qv.y;
        Qt[((c4 << 2) + 2) * 68 + r] = qv.z;
        Qt[((c4 << 2) + 3) * 68 + r] = qv.w;
    }
    if (tid < 64) { ms[tid] = NEG_INF; ls[tid] = 0.0f; }

    float o[4][8];
    #pragma unroll
    for (int i = 0; i < 4; i++)
        #pragma unroll
        for (int j = 0; j < 8; j++) o[i][j] = 0.0f;

    __syncthreads();

    const int ktiles = qb + 1;
    for (int kt = 0; kt < ktiles; kt++) {
        const int k0 = kt * 64;
        // load K (transposed) and V tiles
        #pragma unroll
        for (int i = 0; i < 8; i++) {
            int lin = tid + (i << 8);
            int r  = lin >> 5;
            int c4 = lin & 31;
            size_t goff = ((size_t)(b * SEQ + k0 + r) * EMB) + h * HDIM + (c4 << 2);
            float4 kv = *(const float4*)(K + goff);
            Kt[((c4 << 2) + 0) * 68 + r] = kv.x;
            Kt[((c4 << 2) + 1) * 68 + r] = kv.y;
            Kt[((c4 << 2) + 2) * 68 + r] = kv.z;
            Kt[((c4 << 2) + 3) * 68 + r] = kv.w;
            float4 vv = *(const float4*)(V + goff);
            *(float4*)&Vs[r * 132 + (c4 << 2)] = vv;
        }
        __syncthreads();

        // S = Q K^T  (4 rows x 4 cols per thread)
        float sacc[4][4];
        #pragma unroll
        for (int i = 0; i < 4; i++)
            #pragma unroll
            for (int j = 0; j < 4; j++) sacc[i][j] = 0.0f;

        #pragma unroll 4
        for (int d = 0; d < 128; d++) {
            float4 qv = *(float4*)&Qt[d * 68 + (ty << 2)];
            float4 kv = *(float4*)&Kt[d * 68 + (tx << 2)];
            float qa[4] = {qv.x, qv.y, qv.z, qv.w};
            float ka[4] = {kv.x, kv.y, kv.z, kv.w};
            #pragma unroll
            for (int i = 0; i < 4; i++)
                #pragma unroll
                for (int j = 0; j < 4; j++)
                    sacc[i][j] = fmaf(qa[i], ka[j], sacc[i][j]);
        }

        // mask + write transposed Pt[c][r]
        #pragma unroll
        for (int j = 0; j < 4; j++) {
            int c = (tx << 2) + j;
            float4 pv;
            float t0 = sacc[0][j] * ATT_SCALE;
            float t1 = sacc[1][j] * ATT_SCALE;
            float t2 = sacc[2][j] * ATT_SCALE;
            float t3 = sacc[3][j] * ATT_SCALE;
            pv.x = (k0 + c > q0 + (ty << 2) + 0) ? NEG_INF : t0;
            pv.y = (k0 + c > q0 + (ty << 2) + 1) ? NEG_INF : t1;
            pv.z = (k0 + c > q0 + (ty << 2) + 2) ? NEG_INF : t2;
            pv.w = (k0 + c > q0 + (ty << 2) + 3) ? NEG_INF : t3;
            *(float4*)&Pt[c * 68 + (ty << 2)] = pv;
        }
        __syncthreads();

        // online softmax: 4 threads per q-row
        {
            int r  = tid >> 2;
            int qd = tid & 3;
            float mx = NEG_INF;
            #pragma unroll
            for (int cc = 0; cc < 16; cc++)
                mx = fmaxf(mx, Pt[(qd * 16 + cc) * 68 + r]);
            mx = fmaxf(mx, __shfl_xor_sync(0xffffffffu, mx, 1));
            mx = fmaxf(mx, __shfl_xor_sync(0xffffffffu, mx, 2));
            float m_old = ms[r];
            float m_new = fmaxf(m_old, mx);
            float sum = 0.0f;
            #pragma unroll
            for (int cc = 0; cc < 16; cc++) {
                int cidx = (qd * 16 + cc) * 68 + r;
                float p = __expf(Pt[cidx] - m_new);
                Pt[cidx] = p;
                sum += p;
            }
            sum += __shfl_xor_sync(0xffffffffu, sum, 1);
            sum += __shfl_xor_sync(0xffffffffu, sum, 2);
            if (qd == 0) {
                float sc = __expf(m_old - m_new);
                ms[r] = m_new;
                ss[r] = sc;
                ls[r] = ls[r] * sc + sum;
            }
        }
        __syncthreads();

        // rescale O, then O += P @ V
        {
            float rs[4];
            #pragma unroll
            for (int i = 0; i < 4; i++) rs[i] = ss[(ty << 2) + i];
            #pragma unroll
            for (int i = 0; i < 4; i++)
                #pragma unroll
                for (int j = 0; j < 8; j++) o[i][j] *= rs[i];

            #pragma unroll 2
            for (int kk = 0; kk < 64; kk++) {
                float4 pv = *(float4*)&Pt[kk * 68 + (ty << 2)];
                float4 v0 = *(float4*)&Vs[kk * 132 + (tx << 2)];
                float4 v1 = *(float4*)&Vs[kk * 132 + 64 + (tx << 2)];
                float pr[4] = {pv.x, pv.y, pv.z, pv.w};
                float vv[8] = {v0.x, v0.y, v0.z, v0.w, v1.x, v1.y, v1.z, v1.w};
                #pragma unroll
                for (int i = 0; i < 4; i++)
                    #pragma unroll
                    for (int j = 0; j < 8; j++)
                        o[i][j] = fmaf(pr[i], vv[j], o[i][j]);
            }
        }
        __syncthreads();
    }

    // epilogue: divide by l, write Y (layout [b, s, h, d])
    #pragma unroll
    for (int i = 0; i < 4; i++) {
        int r = (ty << 2) + i;
        float inv = 1.0f / ls[r];
        float* dst = Y + ((size_t)(b * SEQ + q0 + r) * EMB) + h * HDIM;
        float4 w0, w1;
        w0.x = o[i][0] * inv; w0.y = o[i][1] * inv; w0.z = o[i][2] * inv; w0.w = o[i][3] * inv;
        w1.x = o[i][4] * inv; w1.y = o[i][5] * inv; w1.z = o[i][6] * inv; w1.w = o[i][7] * inv;
        *(float4*)(dst + (tx << 2))      = w0;
        *(float4*)(dst + 64 + (tx << 2)) = w1;
    }
}

// ---------------------------------------------------------------------------
// Launch
// ---------------------------------------------------------------------------
extern "C" void kernel_launch(void* const* d_in, const int* in_sizes, int n_in,
                              void* d_out, int out_size) {
    const float* x  = (const float*)d_in[0];
    const float* wq = (const float*)d_in[1];
    const float* wk = (const float*)d_in[2];
    const float* wv = (const float*)d_in[3];
    const float* wo = (const float*)d_in[4];
    float* out = (float*)d_out;

    float *qp, *kp, *vp, *yp, *cp, *sp;
    cudaGetSymbolAddress((void**)&qp, g_Q);
    cudaGetSymbolAddress((void**)&kp, g_K);
    cudaGetSymbolAddress((void**)&vp, g_V);
    cudaGetSymbolAddress((void**)&yp, g_Y);
    cudaGetSymbolAddress((void**)&cp, g_cos);
    cudaGetSymbolAddress((void**)&sp, g_sin);

    // RoPE tables
    rope_table_kernel<<<(SEQ * (HDIM/2) + 255) / 256, 256>>>(cp, sp);

    // QKV projections
    dim3 gg(EMB / 128, MTOT / 128);   // (16, 32)
    gemm128<<<gg, 256>>>(x, wq, qp, MTOT, EMB, EMB);
    gemm128<<<gg, 256>>>(x, wk, kp, MTOT, EMB, EMB);
    gemm128<<<gg, 256>>>(x, wv, vp, MTOT, EMB, EMB);

    // RoPE on Q, K
    int rope_threads = MTOT * NHEAD * (HDIM/2);
    rope_kernel<<<(rope_threads + 255) / 256, 256>>>(qp, kp, cp, sp);

    // Attention
    cudaFuncSetAttribute(attn_kernel, cudaFuncAttributeMaxDynamicSharedMemorySize,
                         ATTN_SMEM_BYTES);
    dim3 ag(SEQ / 64, NHEAD, BATCH);  // (32, 16, 2)
    attn_kernel<<<ag, 256, ATTN_SMEM_BYTES>>>(qp, kp, vp, yp);

    // Output projection
    gemm128<<<gg, 256>>>(yp, wo, out, MTOT, EMB, EMB);
}

// round 8
// speedup vs baseline: 1.6638x; 1.6629x over previous
#include <cuda_runtime.h>
#include <cuda_bf16.h>
#include <math.h>
#include <stdint.h>

// Problem constants
#define BATCH   2
#define SEQ     2048
#define EMB     2048
#define NHEAD   16
#define HDIM    128
#define MTOT    (BATCH*SEQ)          // 4096
#define GK      2048
#define GN      2048
#define NEG_INF (-1e30f)
#define ATT_SCALE 0.08838834764831845f  // 1/sqrt(128)

// Scratch (device globals: allocation-free)
__device__ float g_Q[MTOT*EMB];
__device__ float g_K[MTOT*EMB];
__device__ float g_V[MTOT*EMB];
__device__ float g_Y[MTOT*EMB];
__device__ float g_cos[SEQ*(HDIM/2)];
__device__ float g_sin[SEQ*(HDIM/2)];
__device__ __nv_bfloat16 g_Ahi[MTOT*GK];   // activation hi
__device__ __nv_bfloat16 g_Alo[MTOT*GK];   // activation lo
__device__ __nv_bfloat16 g_Whi[GN*GK];     // transposed weight hi [N,K]
__device__ __nv_bfloat16 g_Wlo[GN*GK];     // transposed weight lo [N,K]

// ============================================================================
// PTX helpers (portable: sm_80+ instructions only, safe for base sm_103 target)
// ============================================================================
__device__ __forceinline__ uint32_t smem_u32(const void* p) {
    uint32_t a;
    asm("{ .reg .u64 t; cvta.to.shared.u64 t, %1; cvt.u32.u64 %0, t; }"
        : "=r"(a) : "l"(p));
    return a;
}

#define CP_ASYNC16(dst, src) \
    asm volatile("cp.async.cg.shared.global [%0], [%1], 16;" \
                 :: "r"(dst), "l"(src) : "memory")
#define CP_COMMIT() asm volatile("cp.async.commit_group;" ::: "memory")
#define CP_WAIT1()  asm volatile("cp.async.wait_group 1;" ::: "memory")
#define CP_WAIT0()  asm volatile("cp.async.wait_group 0;" ::: "memory")

#define LDSM4(r, addr)                                                         \
    asm volatile("ldmatrix.sync.aligned.m8n8.x4.shared.b16 {%0,%1,%2,%3}, [%4];" \
                 : "=r"((r)[0]), "=r"((r)[1]), "=r"((r)[2]), "=r"((r)[3])      \
                 : "r"(addr))

#define MMA16816(d, a, b)                                                      \
    asm volatile(                                                              \
        "mma.sync.aligned.m16n8k16.row.col.f32.bf16.bf16.f32 "                 \
        "{%0,%1,%2,%3}, {%4,%5,%6,%7}, {%8,%9}, {%0,%1,%2,%3};"                \
        : "+f"((d)[0]), "+f"((d)[1]), "+f"((d)[2]), "+f"((d)[3])               \
        : "r"((a)[0]), "r"((a)[1]), "r"((a)[2]), "r"((a)[3]),                  \
          "r"((b)[0]), "r"((b)[1]))

// ============================================================================
// Prep kernels: fp32 -> (hi,lo) bf16 split; weight transpose+split
// ============================================================================
__global__ void split_bf16_kernel(const float* __restrict__ X,
                                  __nv_bfloat16* __restrict__ hi,
                                  __nv_bfloat16* __restrict__ lo, int n4) {
    int i = blockIdx.x * blockDim.x + threadIdx.x;
    if (i >= n4) return;
    float4 v = ((const float4*)X)[i];
    __nv_bfloat16 h0 = __float2bfloat16(v.x);
    __nv_bfloat16 h1 = __float2bfloat16(v.y);
    __nv_bfloat16 h2 = __float2bfloat16(v.z);
    __nv_bfloat16 h3 = __float2bfloat16(v.w);
    __nv_bfloat16 l0 = __float2bfloat16(v.x - __bfloat162float(h0));
    __nv_bfloat16 l1 = __float2bfloat16(v.y - __bfloat162float(h1));
    __nv_bfloat16 l2 = __float2bfloat16(v.z - __bfloat162float(h2));
    __nv_bfloat16 l3 = __float2bfloat16(v.w - __bfloat162float(h3));
    __nv_bfloat162* hp = (__nv_bfloat162*)hi;
    __nv_bfloat162* lp = (__nv_bfloat162*)lo;
    hp[i*2+0] = __nv_bfloat162(h0, h1);
    hp[i*2+1] = __nv_bfloat162(h2, h3);
    lp[i*2+0] = __nv_bfloat162(l0, l1);
    lp[i*2+1] = __nv_bfloat162(l2, l3);
}

// W[K,N] fp32 -> Wt_hi/Wt_lo [N,K] bf16
__global__ void transpose_split_kernel(const float* __restrict__ W,
                                       __nv_bfloat16* __restrict__ hi,
                                       __nv_bfloat16* __restrict__ lo) {
    __shared__ float t[32][33];
    int bx = blockIdx.x * 32;   // n base
    int by = blockIdx.y * 32;   // k base
    int tx = threadIdx.x, ty = threadIdx.y;
    #pragma unroll
    for (int j = 0; j < 32; j += 8)
        t[ty + j][tx] = W[(size_t)(by + ty + j) * GN + bx + tx];
    __syncthreads();
    #pragma unroll
    for (int j = 0; j < 32; j += 8) {
        float v = t[tx][ty + j];
        __nv_bfloat16 h = __float2bfloat16(v);
        __nv_bfloat16 l = __float2bfloat16(v - __bfloat162float(h));
        size_t o = (size_t)(bx + ty + j) * GK + by + tx;
        hi[o] = h;
        lo[o] = l;
    }
}

// ============================================================================
// mma.sync split-bf16 GEMM: C[M,N](fp32) = A[M,K] * W[K,N]
// A as Ahi/Alo [M,K] bf16; W as Whi/Wlo [N,K] bf16 (pre-transposed).
// 128x128 CTA tile, BK=32, 8 warps (2x4), warp tile 64x32.
// cp.async double buffer; ldmatrix.x4 with conflict-free swizzle.
// D += Ahi*Bhi + Ahi*Blo + Alo*Bhi  (fp32 accumulate in HMMA)
// ============================================================================
#define NKB (GK / 32)            // 64 k-chunks
#define TILE_B  8192             // one 128x32 bf16 tile
#define STAGE_B (4*TILE_B)       // 32 KB
#define GEMM_SMEM_BYTES (2*STAGE_B)

// swizzle: 16B slot within 64B row, slot ^= (row>>1)&3  (period-8 in rows)
__device__ __forceinline__ uint32_t tile_off(uint32_t row, uint32_t slot) {
    return row * 64 + ((slot ^ ((row >> 1) & 3)) << 4);
}

__global__ __launch_bounds__(256) void tc_gemm(
    const __nv_bfloat16* __restrict__ Ahi, const __nv_bfloat16* __restrict__ Alo,
    const __nv_bfloat16* __restrict__ Bhi, const __nv_bfloat16* __restrict__ Blo,
    float* __restrict__ C) {
    extern __shared__ char smraw[];
    const uint32_t base = smem_u32(smraw);
    const int tid  = threadIdx.x;
    const int wid  = tid >> 5;
    const int lane = tid & 31;
    const int m0 = blockIdx.y * 128;
    const int n0 = blockIdx.x * 128;
    const int wm = wid >> 2;      // 0..1
    const int wn = wid & 3;       // 0..3

    const __nv_bfloat16* srcs[4] = {Ahi, Alo, Bhi, Blo};
    const int rowbase[4] = {m0, m0, n0, n0};

    float acc[4][4][4];
    #pragma unroll
    for (int mt = 0; mt < 4; mt++)
        #pragma unroll
        for (int nt = 0; nt < 4; nt++)
            #pragma unroll
            for (int e = 0; e < 4; e++) acc[mt][nt][e] = 0.0f;

    // ldmatrix per-lane addressing
    const uint32_t a_row  = wm * 64 + (lane & 15);
    const int      a_kadd = lane >> 4;             // 0/1
    const uint32_t b_row  = wn * 32 + (lane & 7) + ((lane & 16) >> 1);
    const int      b_kadd = (lane >> 3) & 1;       // 0/1

    // async-copy issue: 8 x 16B per thread per stage
    auto issue = [&](int kb) {
        const int kcol = kb * 32;
        const uint32_t stg = base + (kb & 1) * STAGE_B;
        #pragma unroll
        for (int t = 0; t < 4; t++)
            #pragma unroll
            for (int i = 0; i < 2; i++) {
                int c = i * 256 + tid;           // 0..511
                uint32_t row = c >> 2;
                uint32_t cs  = c & 3;
                const __nv_bfloat16* src =
                    srcs[t] + (size_t)(rowbase[t] + row) * GK + kcol + cs * 8;
                uint32_t dst = stg + t * TILE_B + tile_off(row, cs);
                CP_ASYNC16(dst, src);
            }
        CP_COMMIT();
    };

    issue(0);

    for (int kb = 0; kb < NKB; kb++) {
        if (kb + 1 < NKB) { issue(kb + 1); CP_WAIT1(); }
        else              { CP_WAIT0(); }
        __syncthreads();

        const uint32_t st = base + (kb & 1) * STAGE_B;

        #pragma unroll
        for (int ks = 0; ks < 2; ks++) {
            uint32_t ahi[4][4], alo[4][4], bhi[4][2], blo[4][2];
            #pragma unroll
            for (int mt = 0; mt < 4; mt++) {
                uint32_t row = a_row + mt * 16;
                uint32_t ad  = st + tile_off(row, (uint32_t)(ks * 2 + a_kadd));
                LDSM4(ahi[mt], ad);
                LDSM4(alo[mt], ad + TILE_B);
            }
            #pragma unroll
            for (int np = 0; np < 2; np++) {
                uint32_t row = b_row + np * 16;
                uint32_t bd  = st + 2 * TILE_B + tile_off(row, (uint32_t)(ks * 2 + b_kadd));
                uint32_t r[4];
                LDSM4(r, bd);
                bhi[np*2][0] = r[0]; bhi[np*2][1] = r[1];
                bhi[np*2+1][0] = r[2]; bhi[np*2+1][1] = r[3];
                LDSM4(r, bd + TILE_B);
                blo[np*2][0] = r[0]; blo[np*2][1] = r[1];
                blo[np*2+1][0] = r[2]; blo[np*2+1][1] = r[3];
            }
            #pragma unroll
            for (int mt = 0; mt < 4; mt++)
                #pragma unroll
                for (int nt = 0; nt < 4; nt++) {
                    MMA16816(acc[mt][nt], ahi[mt], bhi[nt]);
                    MMA16816(acc[mt][nt], ahi[mt], blo[nt]);
                    MMA16816(acc[mt][nt], alo[mt], bhi[nt]);
                }
        }
        __syncthreads();
    }

    // epilogue: fragment -> gmem (fp32)
    const int r0  = m0 + wm * 64 + (lane >> 2);
    const int col = n0 + wn * 32 + (lane & 3) * 2;
    #pragma unroll
    for (int mt = 0; mt < 4; mt++)
        #pragma unroll
        for (int nt = 0; nt < 4; nt++) {
            float* d = acc[mt][nt];
            size_t o0 = (size_t)(r0 + mt * 16)     * GN + col + nt * 8;
            size_t o1 = (size_t)(r0 + mt * 16 + 8) * GN + col + nt * 8;
            *(float2*)(C + o0) = make_float2(d[0], d[1]);
            *(float2*)(C + o1) = make_float2(d[2], d[3]);
        }
}

// ---------------------------------------------------------------------------
// RoPE table
// ---------------------------------------------------------------------------
__global__ void rope_table_kernel(float* ct, float* st) {
    int idx = blockIdx.x * blockDim.x + threadIdx.x;
    if (idx >= SEQ * (HDIM/2)) return;
    int s = idx >> 6;
    int j = idx & 63;
    float inv = powf(10000.0f, -((float)(2*j)) / 128.0f);
    float a = (float)s * inv;
    ct[idx] = cosf(a);
    st[idx] = sinf(a);
}

// ---------------------------------------------------------------------------
// RoPE application (in-place on Q and K, layout [b, s, h, d])
// ---------------------------------------------------------------------------
__global__ void rope_kernel(float* Q, float* K, const float* __restrict__ ct,
                            const float* __restrict__ st) {
    int idx = blockIdx.x * blockDim.x + threadIdx.x;
    if (idx >= MTOT * NHEAD * (HDIM/2)) return;
    int j   = idx & 63;
    int rem = idx >> 6;
    int s   = (rem >> 4) & (SEQ - 1);
    float c  = ct[(s << 6) + j];
    float sn = st[(s << 6) + j];
    size_t off = ((size_t)rem << 7) + (j << 1);
    float2 q = *(float2*)(Q + off);
    float2 k = *(float2*)(K + off);
    *(float2*)(Q + off) = make_float2(q.x*c - q.y*sn, q.x*sn + q.y*c);
    *(float2*)(K + off) = make_float2(k.x*c - k.y*sn, k.x*sn + k.y*c);
}

// ---------------------------------------------------------------------------
// Causal flash attention, fp32 (unchanged passing version)
// ---------------------------------------------------------------------------
#define QT_OFF  0
#define KT_OFF  (128*68)
#define VS_OFF  (KT_OFF + 128*68)
#define PT_OFF  (VS_OFF + 64*132)
#define MS_OFF  (PT_OFF + 64*68)
#define LS_OFF  (MS_OFF + 64)
#define SS_OFF  (LS_OFF + 64)
#define ATTN_SMEM_FLOATS (SS_OFF + 64)
#define ATTN_SMEM_BYTES  (ATTN_SMEM_FLOATS * 4)

__global__ __launch_bounds__(256) void attn_kernel(const float* __restrict__ Q,
                                                   const float* __restrict__ K,
                                                   const float* __restrict__ V,
                                                   float* __restrict__ Y) {
    extern __shared__ float sm[];
    float* Qt = sm + QT_OFF;
    float* Kt = sm + KT_OFF;
    float* Vs = sm + VS_OFF;
    float* Pt = sm + PT_OFF;
    float* ms = sm + MS_OFF;
    float* ls = sm + LS_OFF;
    float* ss = sm + SS_OFF;

    const int tid = threadIdx.x;
    const int ty = tid >> 4;
    const int tx = tid & 15;
    const int qb = blockIdx.x;
    const int h  = blockIdx.y;
    const int b  = blockIdx.z;
    const int q0 = qb * 64;

    #pragma unroll
    for (int i = 0; i < 8; i++) {
        int lin = tid + (i << 8);
        int r  = lin >> 5;
        int c4 = lin & 31;
        const float* src = Q + ((size_t)(b * SEQ + q0 + r) * EMB) + h * HDIM + (c4 << 2);
        float4 qv = *(const float4*)src;
        Qt[((c4 << 2) + 0) * 68 + r] = qv.x;
        Qt[((c4 << 2) + 1) * 68 + r] = qv.y;
        Qt[((c4 << 2) + 2) * 68 + r] = qv.z;
        Qt[((c4 << 2) + 3) * 68 + r] = qv.w;
    }
    if (tid < 64) { ms[tid] = NEG_INF; ls[tid] = 0.0f; }

    float o[4][8];
    #pragma unroll
    for (int i = 0; i < 4; i++)
        #pragma unroll
        for (int j = 0; j < 8; j++) o[i][j] = 0.0f;

    __syncthreads();

    const int ktiles = qb + 1;
    for (int kt = 0; kt < ktiles; kt++) {
        const int k0 = kt * 64;
        #pragma unroll
        for (int i = 0; i < 8; i++) {
            int lin = tid + (i << 8);
            int r  = lin >> 5;
            int c4 = lin & 31;
            size_t goff = ((size_t)(b * SEQ + k0 + r) * EMB) + h * HDIM + (c4 << 2);
            float4 kv = *(const float4*)(K + goff);
            Kt[((c4 << 2) + 0) * 68 + r] = kv.x;
            Kt[((c4 << 2) + 1) * 68 + r] = kv.y;
            Kt[((c4 << 2) + 2) * 68 + r] = kv.z;
            Kt[((c4 << 2) + 3) * 68 + r] = kv.w;
            float4 vv = *(const float4*)(V + goff);
            *(float4*)&Vs[r * 132 + (c4 << 2)] = vv;
        }
        __syncthreads();

        float sacc[4][4];
        #pragma unroll
        for (int i = 0; i < 4; i++)
            #pragma unroll
            for (int j = 0; j < 4; j++) sacc[i][j] = 0.0f;

        #pragma unroll 4
        for (int d = 0; d < 128; d++) {
            float4 qv = *(float4*)&Qt[d * 68 + (ty << 2)];
            float4 kv = *(float4*)&Kt[d * 68 + (tx << 2)];
            float qa[4] = {qv.x, qv.y, qv.z, qv.w};
            float ka[4] = {kv.x, kv.y, kv.z, kv.w};
            #pragma unroll
            for (int i = 0; i < 4; i++)
                #pragma unroll
                for (int j = 0; j < 4; j++)
                    sacc[i][j] = fmaf(qa[i], ka[j], sacc[i][j]);
        }

        #pragma unroll
        for (int j = 0; j < 4; j++) {
            int c = (tx << 2) + j;
            float4 pv;
            float t0 = sacc[0][j] * ATT_SCALE;
            float t1 = sacc[1][j] * ATT_SCALE;
            float t2 = sacc[2][j] * ATT_SCALE;
            float t3 = sacc[3][j] * ATT_SCALE;
            pv.x = (k0 + c > q0 + (ty << 2) + 0) ? NEG_INF : t0;
            pv.y = (k0 + c > q0 + (ty << 2) + 1) ? NEG_INF : t1;
            pv.z = (k0 + c > q0 + (ty << 2) + 2) ? NEG_INF : t2;
            pv.w = (k0 + c > q0 + (ty << 2) + 3) ? NEG_INF : t3;
            *(float4*)&Pt[c * 68 + (ty << 2)] = pv;
        }
        __syncthreads();

        {
            int r  = tid >> 2;
            int qd = tid & 3;
            float mx = NEG_INF;
            #pragma unroll
            for (int cc = 0; cc < 16; cc++)
                mx = fmaxf(mx, Pt[(qd * 16 + cc) * 68 + r]);
            mx = fmaxf(mx, __shfl_xor_sync(0xffffffffu, mx, 1));
            mx = fmaxf(mx, __shfl_xor_sync(0xffffffffu, mx, 2));
            float m_old = ms[r];
            float m_new = fmaxf(m_old, mx);
            float sum = 0.0f;
            #pragma unroll
            for (int cc = 0; cc < 16; cc++) {
                int cidx = (qd * 16 + cc) * 68 + r;
                float p = __expf(Pt[cidx] - m_new);
                Pt[cidx] = p;
                sum += p;
            }
            sum += __shfl_xor_sync(0xffffffffu, sum, 1);
            sum += __shfl_xor_sync(0xffffffffu, sum, 2);
            if (qd == 0) {
                float sc = __expf(m_old - m_new);
                ms[r] = m_new;
                ss[r] = sc;
                ls[r] = ls[r] * sc + sum;
            }
        }
        __syncthreads();

        {
            float rs[4];
            #pragma unroll
            for (int i = 0; i < 4; i++) rs[i] = ss[(ty << 2) + i];
            #pragma unroll
            for (int i = 0; i < 4; i++)
                #pragma unroll
                for (int j = 0; j < 8; j++) o[i][j] *= rs[i];

            #pragma unroll 2
            for (int kk = 0; kk < 64; kk++) {
                float4 pv = *(float4*)&Pt[kk * 68 + (ty << 2)];
                float4 v0 = *(float4*)&Vs[kk * 132 + (tx << 2)];
                float4 v1 = *(float4*)&Vs[kk * 132 + 64 + (tx << 2)];
                float pr[4] = {pv.x, pv.y, pv.z, pv.w};
                float vv[8] = {v0.x, v0.y, v0.z, v0.w, v1.x, v1.y, v1.z, v1.w};
                #pragma unroll
                for (int i = 0; i < 4; i++)
                    #pragma unroll
                    for (int j = 0; j < 8; j++)
                        o[i][j] = fmaf(pr[i], vv[j], o[i][j]);
            }
        }
        __syncthreads();
    }

    #pragma unroll
    for (int i = 0; i < 4; i++) {
        int r = (ty << 2) + i;
        float inv = 1.0f / ls[r];
        float* dst = Y + ((size_t)(b * SEQ + q0 + r) * EMB) + h * HDIM;
        float4 w0, w1;
        w0.x = o[i][0] * inv; w0.y = o[i][1] * inv; w0.z = o[i][2] * inv; w0.w = o[i][3] * inv;
        w1.x = o[i][4] * inv; w1.y = o[i][5] * inv; w1.z = o[i][6] * inv; w1.w = o[i][7] * inv;
        *(float4*)(dst + (tx << 2))      = w0;
        *(float4*)(dst + 64 + (tx << 2)) = w1;
    }
}

// ---------------------------------------------------------------------------
// Launch
// ---------------------------------------------------------------------------
extern "C" void kernel_launch(void* const* d_in, const int* in_sizes, int n_in,
                              void* d_out, int out_size) {
    const float* x  = (const float*)d_in[0];
    const float* wq = (const float*)d_in[1];
    const float* wk = (const float*)d_in[2];
    const float* wv = (const float*)d_in[3];
    const float* wo = (const float*)d_in[4];
    float* out = (float*)d_out;

    float *qp, *kp, *vp, *yp, *cp, *sp;
    __nv_bfloat16 *ahi, *alo, *whi, *wlo;
    cudaGetSymbolAddress((void**)&qp, g_Q);
    cudaGetSymbolAddress((void**)&kp, g_K);
    cudaGetSymbolAddress((void**)&vp, g_V);
    cudaGetSymbolAddress((void**)&yp, g_Y);
    cudaGetSymbolAddress((void**)&cp, g_cos);
    cudaGetSymbolAddress((void**)&sp, g_sin);
    cudaGetSymbolAddress((void**)&ahi, g_Ahi);
    cudaGetSymbolAddress((void**)&alo, g_Alo);
    cudaGetSymbolAddress((void**)&whi, g_Whi);
    cudaGetSymbolAddress((void**)&wlo, g_Wlo);

    cudaFuncSetAttribute(tc_gemm, cudaFuncAttributeMaxDynamicSharedMemorySize,
                         GEMM_SMEM_BYTES);
    cudaFuncSetAttribute(attn_kernel, cudaFuncAttributeMaxDynamicSharedMemorySize,
                         ATTN_SMEM_BYTES);

    // RoPE tables
    rope_table_kernel<<<(SEQ * (HDIM/2) + 255) / 256, 256>>>(cp, sp);

    // Split activations x -> bf16 hi/lo
    int n4 = MTOT * GK / 4;
    split_bf16_kernel<<<(n4 + 255) / 256, 256>>>(x, ahi, alo, n4);

    dim3 tg(32, 8);
    dim3 tgrid(GN / 32, GK / 32);
    dim3 gg(GN / 128, MTOT / 128);   // (16, 32)

    // Q = x @ wq
    transpose_split_kernel<<<tgrid, tg>>>(wq, whi, wlo);
    tc_gemm<<<gg, 256, GEMM_SMEM_BYTES>>>(ahi, alo, whi, wlo, qp);
    // K = x @ wk
    transpose_split_kernel<<<tgrid, tg>>>(wk, whi, wlo);
    tc_gemm<<<gg, 256, GEMM_SMEM_BYTES>>>(ahi, alo, whi, wlo, kp);
    // V = x @ wv
    transpose_split_kernel<<<tgrid, tg>>>(wv, whi, wlo);
    tc_gemm<<<gg, 256, GEMM_SMEM_BYTES>>>(ahi, alo, whi, wlo, vp);

    // RoPE on Q, K
    int rope_threads = MTOT * NHEAD * (HDIM/2);
    rope_kernel<<<(rope_threads + 255) / 256, 256>>>(qp, kp, cp, sp);

    // Attention
    dim3 ag(SEQ / 64, NHEAD, BATCH);  // (32, 16, 2)
    attn_kernel<<<ag, 256, ATTN_SMEM_BYTES>>>(qp, kp, vp, yp);

    // out = y @ wo
    split_bf16_kernel<<<(n4 + 255) / 256, 256>>>(yp, ahi, alo, n4);
    transpose_split_kernel<<<tgrid, tg>>>(wo, whi, wlo);
    tc_gemm<<<gg, 256, GEMM_SMEM_BYTES>>>(ahi, alo, whi, wlo, out);
}

// round 11
// speedup vs baseline: 2.9968x; 1.8012x over previous
#include <cuda_runtime.h>
#include <cuda_bf16.h>
#include <math.h>
#include <stdint.h>

// Problem constants
#define BATCH   2
#define SEQ     2048
#define EMB     2048
#define NHEAD   16
#define HDIM    128
#define MTOT    (BATCH*SEQ)          // 4096
#define GK      2048
#define GN      2048
#define ATT_SCALE 0.08838834764831845f  // 1/sqrt(128)

// Scratch (device globals: allocation-free)
__device__ float g_Q[MTOT*EMB];
__device__ float g_K[MTOT*EMB];
__device__ float g_V[MTOT*EMB];
__device__ float g_Y[MTOT*EMB];
__device__ float g_cos[SEQ*(HDIM/2)];
__device__ float g_sin[SEQ*(HDIM/2)];
__device__ __nv_bfloat16 g_Ahi[MTOT*GK];
__device__ __nv_bfloat16 g_Alo[MTOT*GK];
__device__ __nv_bfloat16 g_Whi[GN*GK];
__device__ __nv_bfloat16 g_Wlo[GN*GK];
__device__ __nv_bfloat16 g_Qhi[MTOT*EMB];
__device__ __nv_bfloat16 g_Qlo[MTOT*EMB];
__device__ __nv_bfloat16 g_Khi[MTOT*EMB];
__device__ __nv_bfloat16 g_Klo[MTOT*EMB];
__device__ __nv_bfloat16 g_Vthi[MTOT*EMB];  // [b,h,d,s]
__device__ __nv_bfloat16 g_Vtlo[MTOT*EMB];  // [b,h,d,s]

// ============================================================================
// PTX helpers (portable sm_80+ only)
// ============================================================================
__device__ __forceinline__ uint32_t smem_u32(const void* p) {
    uint32_t a;
    asm("{ .reg .u64 t; cvta.to.shared.u64 t, %1; cvt.u32.u64 %0, t; }"
        : "=r"(a) : "l"(p));
    return a;
}

#define CP_ASYNC16(dst, src) \
    asm volatile("cp.async.cg.shared.global [%0], [%1], 16;" \
                 :: "r"(dst), "l"(src) : "memory")
#define CP_COMMIT() asm volatile("cp.async.commit_group;" ::: "memory")
#define CP_WAIT1()  asm volatile("cp.async.wait_group 1;" ::: "memory")
#define CP_WAIT0()  asm volatile("cp.async.wait_group 0;" ::: "memory")

#define LDSM4(r, addr)                                                         \
    asm volatile("ldmatrix.sync.aligned.m8n8.x4.shared.b16 {%0,%1,%2,%3}, [%4];" \
                 : "=r"((r)[0]), "=r"((r)[1]), "=r"((r)[2]), "=r"((r)[3])      \
                 : "r"(addr))

#define MMA16816(d, a, b)                                                      \
    asm volatile(                                                              \
        "mma.sync.aligned.m16n8k16.row.col.f32.bf16.bf16.f32 "                 \
        "{%0,%1,%2,%3}, {%4,%5,%6,%7}, {%8,%9}, {%0,%1,%2,%3};"                \
        : "+f"((d)[0]), "+f"((d)[1]), "+f"((d)[2]), "+f"((d)[3])               \
        : "r"((a)[0]), "r"((a)[1]), "r"((a)[2]), "r"((a)[3]),                  \
          "r"((b)[0]), "r"((b)[1]))

__device__ __forceinline__ uint32_t pack_bf16x2(__nv_bfloat16 x, __nv_bfloat16 y) {
    __nv_bfloat162 v(x, y);
    return *reinterpret_cast<uint32_t*>(&v);
}

// swizzle: 16B slot within 64B row, slot ^= (row>>1)&3  (period-8 in rows)
__device__ __forceinline__ uint32_t tile_off(uint32_t row, uint32_t slot) {
    return row * 64 + ((slot ^ ((row >> 1) & 3)) << 4);
}

// ============================================================================
// Prep kernels
// ============================================================================
__global__ void split_bf16_kernel(const float* __restrict__ X,
                                  __nv_bfloat16* __restrict__ hi,
                                  __nv_bfloat16* __restrict__ lo, int n4) {
    int i = blockIdx.x * blockDim.x + threadIdx.x;
    if (i >= n4) return;
    float4 v = ((const float4*)X)[i];
    __nv_bfloat16 h0 = __float2bfloat16(v.x);
    __nv_bfloat16 h1 = __float2bfloat16(v.y);
    __nv_bfloat16 h2 = __float2bfloat16(v.z);
    __nv_bfloat16 h3 = __float2bfloat16(v.w);
    __nv_bfloat16 l0 = __float2bfloat16(v.x - __bfloat162float(h0));
    __nv_bfloat16 l1 = __float2bfloat16(v.y - __bfloat162float(h1));
    __nv_bfloat16 l2 = __float2bfloat16(v.z - __bfloat162float(h2));
    __nv_bfloat16 l3 = __float2bfloat16(v.w - __bfloat162float(h3));
    __nv_bfloat162* hp = (__nv_bfloat162*)hi;
    __nv_bfloat162* lp = (__nv_bfloat162*)lo;
    hp[i*2+0] = __nv_bfloat162(h0, h1);
    hp[i*2+1] = __nv_bfloat162(h2, h3);
    lp[i*2+0] = __nv_bfloat162(l0, l1);
    lp[i*2+1] = __nv_bfloat162(l2, l3);
}

// W[K,N] fp32 -> Wt_hi/Wt_lo [N,K] bf16
__global__ void transpose_split_kernel(const float* __restrict__ W,
                                       __nv_bfloat16* __restrict__ hi,
                                       __nv_bfloat16* __restrict__ lo) {
    __shared__ float t[32][33];
    int bx = blockIdx.x * 32;
    int by = blockIdx.y * 32;
    int tx = threadIdx.x, ty = threadIdx.y;
    #pragma unroll
    for (int j = 0; j < 32; j += 8)
        t[ty + j][tx] = W[(size_t)(by + ty + j) * GN + bx + tx];
    __syncthreads();
    #pragma unroll
    for (int j = 0; j < 32; j += 8) {
        float v = t[tx][ty + j];
        __nv_bfloat16 h = __float2bfloat16(v);
        __nv_bfloat16 l = __float2bfloat16(v - __bfloat162float(h));
        size_t o = (size_t)(bx + ty + j) * GK + by + tx;
        hi[o] = h;
        lo[o] = l;
    }
}

// V fp32 [b,s,h,d] -> Vt hi/lo [b,h,d,s]
__global__ void vtrans_split_kernel(const float* __restrict__ V,
                                    __nv_bfloat16* __restrict__ hi,
                                    __nv_bfloat16* __restrict__ lo) {
    __shared__ float t[32][33];
    int s0 = blockIdx.x * 32;
    int d0 = blockIdx.y * 32;
    int bh = blockIdx.z;           // b*NHEAD + h
    int b = bh >> 4, h = bh & 15;
    int tx = threadIdx.x, ty = threadIdx.y;
    #pragma unroll
    for (int j = 0; j < 32; j += 8)
        t[ty + j][tx] = V[(size_t)(b * SEQ + s0 + ty + j) * EMB + h * HDIM + d0 + tx];
    __syncthreads();
    #pragma unroll
    for (int j = 0; j < 32; j += 8) {
        float v = t[tx][ty + j];
        __nv_bfloat16 hh = __float2bfloat16(v);
        __nv_bfloat16 ll = __float2bfloat16(v - __bfloat162float(hh));
        size_t o = (size_t)(bh * HDIM + d0 + ty + j) * SEQ + s0 + tx;
        hi[o] = hh;
        lo[o] = ll;
    }
}

// ============================================================================
// mma.sync split-bf16 GEMM (unchanged from passing R8)
// ============================================================================
#define NKB (GK / 32)
#define TILE_B  8192
#define STAGE_B (4*TILE_B)
#define GEMM_SMEM_BYTES (2*STAGE_B)

__global__ __launch_bounds__(256) void tc_gemm(
    const __nv_bfloat16* __restrict__ Ahi, const __nv_bfloat16* __restrict__ Alo,
    const __nv_bfloat16* __restrict__ Bhi, const __nv_bfloat16* __restrict__ Blo,
    float* __restrict__ C) {
    extern __shared__ char smraw[];
    const uint32_t base = smem_u32(smraw);
    const int tid  = threadIdx.x;
    const int wid  = tid >> 5;
    const int lane = tid & 31;
    const int m0 = blockIdx.y * 128;
    const int n0 = blockIdx.x * 128;
    const int wm = wid >> 2;
    const int wn = wid & 3;

    const __nv_bfloat16* srcs[4] = {Ahi, Alo, Bhi, Blo};
    const int rowbase[4] = {m0, m0, n0, n0};

    float acc[4][4][4];
    #pragma unroll
    for (int mt = 0; mt < 4; mt++)
        #pragma unroll
        for (int nt = 0; nt < 4; nt++)
            #pragma unroll
            for (int e = 0; e < 4; e++) acc[mt][nt][e] = 0.0f;

    const uint32_t a_row  = wm * 64 + (lane & 15);
    const int      a_kadd = lane >> 4;
    const uint32_t b_row  = wn * 32 + (lane & 7) + ((lane & 16) >> 1);
    const int      b_kadd = (lane >> 3) & 1;

    auto issue = [&](int kb) {
        const int kcol = kb * 32;
        const uint32_t stg = base + (kb & 1) * STAGE_B;
        #pragma unroll
        for (int t = 0; t < 4; t++)
            #pragma unroll
            for (int i = 0; i < 2; i++) {
                int c = i * 256 + tid;
                uint32_t row = c >> 2;
                uint32_t cs  = c & 3;
                const __nv_bfloat16* src =
                    srcs[t] + (size_t)(rowbase[t] + row) * GK + kcol + cs * 8;
                uint32_t dst = stg + t * TILE_B + tile_off(row, cs);
                CP_ASYNC16(dst, src);
            }
        CP_COMMIT();
    };

    issue(0);

    for (int kb = 0; kb < NKB; kb++) {
        if (kb + 1 < NKB) { issue(kb + 1); CP_WAIT1(); }
        else              { CP_WAIT0(); }
        __syncthreads();

        const uint32_t st = base + (kb & 1) * STAGE_B;

        #pragma unroll
        for (int ks = 0; ks < 2; ks++) {
            uint32_t ahi[4][4], alo[4][4], bhi[4][2], blo[4][2];
            #pragma unroll
            for (int mt = 0; mt < 4; mt++) {
                uint32_t row = a_row + mt * 16;
                uint32_t ad  = st + tile_off(row, (uint32_t)(ks * 2 + a_kadd));
                LDSM4(ahi[mt], ad);
                LDSM4(alo[mt], ad + TILE_B);
            }
            #pragma unroll
            for (int np = 0; np < 2; np++) {
                uint32_t row = b_row + np * 16;
                uint32_t bd  = st + 2 * TILE_B + tile_off(row, (uint32_t)(ks * 2 + b_kadd));
                uint32_t r[4];
                LDSM4(r, bd);
                bhi[np*2][0] = r[0]; bhi[np*2][1] = r[1];
                bhi[np*2+1][0] = r[2]; bhi[np*2+1][1] = r[3];
                LDSM4(r, bd + TILE_B);
                blo[np*2][0] = r[0]; blo[np*2][1] = r[1];
                blo[np*2+1][0] = r[2]; blo[np*2+1][1] = r[3];
            }
            #pragma unroll
            for (int mt = 0; mt < 4; mt++)
                #pragma unroll
                for (int nt = 0; nt < 4; nt++) {
                    MMA16816(acc[mt][nt], ahi[mt], bhi[nt]);
                    MMA16816(acc[mt][nt], ahi[mt], blo[nt]);
                    MMA16816(acc[mt][nt], alo[mt], bhi[nt]);
                }
        }
        __syncthreads();
    }

    const int r0  = m0 + wm * 64 + (lane >> 2);
    const int col = n0 + wn * 32 + (lane & 3) * 2;
    #pragma unroll
    for (int mt = 0; mt < 4; mt++)
        #pragma unroll
        for (int nt = 0; nt < 4; nt++) {
            float* d = acc[mt][nt];
            size_t o0 = (size_t)(r0 + mt * 16)     * GN + col + nt * 8;
            size_t o1 = (size_t)(r0 + mt * 16 + 8) * GN + col + nt * 8;
            *(float2*)(C + o0) = make_float2(d[0], d[1]);
            *(float2*)(C + o1) = make_float2(d[2], d[3]);
        }
}

// ---------------------------------------------------------------------------
// RoPE table
// ---------------------------------------------------------------------------
__global__ void rope_table_kernel(float* ct, float* st) {
    int idx = blockIdx.x * blockDim.x + threadIdx.x;
    if (idx >= SEQ * (HDIM/2)) return;
    int s = idx >> 6;
    int j = idx & 63;
    float inv = powf(10000.0f, -((float)(2*j)) / 128.0f);
    float a = (float)s * inv;
    ct[idx] = cosf(a);
    st[idx] = sinf(a);
}

// ---------------------------------------------------------------------------
// RoPE + hi/lo split: reads fp32 Q,K; writes bf16 hi/lo pairs (layout [b,s,h,d])
// ---------------------------------------------------------------------------
__global__ void rope_split_kernel(const float* __restrict__ Q, const float* __restrict__ K,
                                  const float* __restrict__ ct, const float* __restrict__ st,
                                  __nv_bfloat16* __restrict__ Qhi, __nv_bfloat16* __restrict__ Qlo,
                                  __nv_bfloat16* __restrict__ Khi, __nv_bfloat16* __restrict__ Klo) {
    int idx = blockIdx.x * blockDim.x + threadIdx.x;
    if (idx >= MTOT * NHEAD * (HDIM/2)) return;
    int j   = idx & 63;
    int rem = idx >> 6;
    int s   = (rem >> 4) & (SEQ - 1);
    float c  = ct[(s << 6) + j];
    float sn = st[(s << 6) + j];
    size_t off = ((size_t)rem << 7) + (j << 1);
    float2 q = *(const float2*)(Q + off);
    float2 k = *(const float2*)(K + off);
    float qx = q.x*c - q.y*sn, qy = q.x*sn + q.y*c;
    float kx = k.x*c - k.y*sn, ky = k.x*sn + k.y*c;
    __nv_bfloat16 qhx = __float2bfloat16(qx), qhy = __float2bfloat16(qy);
    __nv_bfloat16 khx = __float2bfloat16(kx), khy = __float2bfloat16(ky);
    *(__nv_bfloat162*)(Qhi + off) = __nv_bfloat162(qhx, qhy);
    *(__nv_bfloat162*)(Qlo + off) = __nv_bfloat162(
        __float2bfloat16(qx - __bfloat162float(qhx)),
        __float2bfloat16(qy - __bfloat162float(qhy)));
    *(__nv_bfloat162*)(Khi + off) = __nv_bfloat162(khx, khy);
    *(__nv_bfloat162*)(Klo + off) = __nv_bfloat162(
        __float2bfloat16(kx - __bfloat162float(khx)),
        __float2bfloat16(ky - __bfloat162float(khy)));
}

// ============================================================================
// Tensor-core causal flash attention (split-bf16, 3-term).
// BQ=128 (8 warps x m16), BK=64, cp.async double-buffered K/V, Q resident.
// smem: Qhi/Qlo [4 chunks][128x32] @ 0/32768;
//       stage s @ 65536+s*65536: Khi(16K) Klo(16K) Vthi(16K) Vtlo(16K)
// ============================================================================
#define ATTN_Q_BYTES     65536
#define ATTN_STAGE_BYTES 65536
#define ATTN_SMEM_BYTES  (ATTN_Q_BYTES + 2*ATTN_STAGE_BYTES)  // 196608

__global__ __launch_bounds__(256, 1) void attn_mma(
    const __nv_bfloat16* __restrict__ Qhi, const __nv_bfloat16* __restrict__ Qlo,
    const __nv_bfloat16* __restrict__ Khi, const __nv_bfloat16* __restrict__ Klo,
    const __nv_bfloat16* __restrict__ Vthi, const __nv_bfloat16* __restrict__ Vtlo,
    float* __restrict__ Y) {
    extern __shared__ char smraw[];
    const uint32_t base = smem_u32(smraw);
    const int tid = threadIdx.x, wid = tid >> 5, lane = tid & 31;
    const int qb = blockIdx.x, h = blockIdx.y, b = blockIdx.z;
    const int q0 = qb * 128;
    const int wm0 = wid * 16;
    const int g = lane >> 2, t4 = lane & 3;
    const int ntiles = 2 * qb + 2;

    const uint32_t a_row = wm0 + (lane & 15);
    const int a_kadd = lane >> 4;
    const uint32_t b_rowbase = (lane & 7) + ((lane & 16) >> 1);
    const int b_kadd = (lane >> 3) & 1;

    // Q load (grouped with stage 0's commit)
    #pragma unroll
    for (int i = 0; i < 8; i++) {
        int c = i * 256 + tid;
        uint32_t row = (c >> 2) & 127, slot = c & 3, kc = c >> 9;
        size_t src = ((size_t)(b * SEQ + q0 + row)) * EMB + h * HDIM + kc * 32 + slot * 8;
        uint32_t dst = base + kc * 8192 + tile_off(row, slot);
        CP_ASYNC16(dst, Qhi + src);
        CP_ASYNC16(dst + 32768, Qlo + src);
    }

    auto issueKV = [&](int kt) {
        const int k0 = kt * 64;
        const uint32_t stg = base + ATTN_Q_BYTES + (kt & 1) * ATTN_STAGE_BYTES;
        #pragma unroll
        for (int i = 0; i < 4; i++) {
            int c = i * 256 + tid;
            {   // K tile: [64 rows][128 cols] -> 4 chunks of [64][32]
                uint32_t row = (c >> 2) & 63, slot = c & 3, kc = c >> 8;
                size_t src = ((size_t)(b * SEQ + k0 + row)) * EMB + h * HDIM + kc * 32 + slot * 8;
                uint32_t dst = stg + kc * 4096 + tile_off(row, slot);
                CP_ASYNC16(dst, Khi + src);
                CP_ASYNC16(dst + 16384, Klo + src);
            }
            {   // Vt tile: [128 d][64 s] -> 2 chunks of [128][32]
                uint32_t row = (c >> 2) & 127, slot = c & 3, sc = c >> 9;
                size_t src = ((size_t)((b * NHEAD + h) * HDIM + row)) * SEQ + k0 + sc * 32 + slot * 8;
                uint32_t dst = stg + 32768 + sc * 8192 + tile_off(row, slot);
                CP_ASYNC16(dst, Vthi + src);
                CP_ASYNC16(dst + 16384, Vtlo + src);
            }
        }
        CP_COMMIT();
    };

    issueKV(0);

    float oacc[16][4];
    #pragma unroll
    for (int nt = 0; nt < 16; nt++)
        #pragma unroll
        for (int e = 0; e < 4; e++) oacc[nt][e] = 0.0f;
    float m0 = -1e30f, m1 = -1e30f, l0 = 0.0f, l1 = 0.0f;

    const int r0g = q0 + wm0 + g;

    for (int kt = 0; kt < ntiles; kt++) {
        if (kt + 1 < ntiles) { issueKV(kt + 1); CP_WAIT1(); }
        else                 { CP_WAIT0(); }
        __syncthreads();

        const int k0 = kt * 64;
        const uint32_t stg = base + ATTN_Q_BYTES + (kt & 1) * ATTN_STAGE_BYTES;

        // ---- S = Q K^T (3-term split) ----
        float sacc[8][4];
        #pragma unroll
        for (int nt = 0; nt < 8; nt++)
            #pragma unroll
            for (int e = 0; e < 4; e++) sacc[nt][e] = 0.0f;

        #pragma unroll
        for (int ks = 0; ks < 8; ks++) {
            uint32_t ah[4], al[4];
            uint32_t qa = base + (ks >> 1) * 8192 +
                          tile_off(a_row, (uint32_t)((ks & 1) * 2 + a_kadd));
            LDSM4(ah, qa);
            LDSM4(al, qa + 32768);
            #pragma unroll
            for (int np = 0; np < 4; np++) {
                uint32_t rh[4], rl[4];
                uint32_t ka = stg + (ks >> 1) * 4096 +
                              tile_off(np * 16 + b_rowbase, (uint32_t)((ks & 1) * 2 + b_kadd));
                LDSM4(rh, ka);
                LDSM4(rl, ka + 16384);
                uint32_t bh0[2] = {rh[0], rh[1]}, bh1[2] = {rh[2], rh[3]};
                uint32_t bl0[2] = {rl[0], rl[1]}, bl1[2] = {rl[2], rl[3]};
                MMA16816(sacc[np*2],   ah, bh0);
                MMA16816(sacc[np*2],   ah, bl0);
                MMA16816(sacc[np*2],   al, bh0);
                MMA16816(sacc[np*2+1], ah, bh1);
                MMA16816(sacc[np*2+1], ah, bl1);
                MMA16816(sacc[np*2+1], al, bh1);
            }
        }

        // ---- scale + causal mask ----
        #pragma unroll
        for (int nt = 0; nt < 8; nt++)
            #pragma unroll
            for (int e = 0; e < 4; e++) sacc[nt][e] *= ATT_SCALE;

        if (k0 + 63 > q0 + wm0) {
            #pragma unroll
            for (int nt = 0; nt < 8; nt++) {
                int c0 = k0 + nt * 8 + t4 * 2;
                if (c0     > r0g)     sacc[nt][0] = -1e30f;
                if (c0 + 1 > r0g)     sacc[nt][1] = -1e30f;
                if (c0     > r0g + 8) sacc[nt][2] = -1e30f;
                if (c0 + 1 > r0g + 8) sacc[nt][3] = -1e30f;
            }
        }

        // ---- online softmax (rows g and g+8) ----
        float mx0 = -1e30f, mx1 = -1e30f;
        #pragma unroll
        for (int nt = 0; nt < 8; nt++) {
            mx0 = fmaxf(mx0, fmaxf(sacc[nt][0], sacc[nt][1]));
            mx1 = fmaxf(mx1, fmaxf(sacc[nt][2], sacc[nt][3]));
        }
        mx0 = fmaxf(mx0, __shfl_xor_sync(0xffffffffu, mx0, 1));
        mx0 = fmaxf(mx0, __shfl_xor_sync(0xffffffffu, mx0, 2));
        mx1 = fmaxf(mx1, __shfl_xor_sync(0xffffffffu, mx1, 1));
        mx1 = fmaxf(mx1, __shfl_xor_sync(0xffffffffu, mx1, 2));
        float mn0 = fmaxf(m0, mx0), mn1 = fmaxf(m1, mx1);
        float sf0 = __expf(m0 - mn0), sf1 = __expf(m1 - mn1);
        m0 = mn0; m1 = mn1;
        float sum0 = 0.0f, sum1 = 0.0f;
        #pragma unroll
        for (int nt = 0; nt < 8; nt++) {
            sacc[nt][0] = __expf(sacc[nt][0] - mn0); sum0 += sacc[nt][0];
            sacc[nt][1] = __expf(sacc[nt][1] - mn0); sum0 += sacc[nt][1];
            sacc[nt][2] = __expf(sacc[nt][2] - mn1); sum1 += sacc[nt][2];
            sacc[nt][3] = __expf(sacc[nt][3] - mn1); sum1 += sacc[nt][3];
        }
        sum0 += __shfl_xor_sync(0xffffffffu, sum0, 1);
        sum0 += __shfl_xor_sync(0xffffffffu, sum0, 2);
        sum1 += __shfl_xor_sync(0xffffffffu, sum1, 1);
        sum1 += __shfl_xor_sync(0xffffffffu, sum1, 2);
        l0 = l0 * sf0 + sum0;
        l1 = l1 * sf1 + sum1;
        #pragma unroll
        for (int nt = 0; nt < 16; nt++) {
            oacc[nt][0] *= sf0; oacc[nt][1] *= sf0;
            oacc[nt][2] *= sf1; oacc[nt][3] *= sf1;
        }

        // ---- P fragments (acc -> A operand, hi/lo split, in-register) ----
        uint32_t pha[4][4], pla[4][4];
        #pragma unroll
        for (int kp = 0; kp < 4; kp++) {
            #pragma unroll
            for (int half = 0; half < 2; half++) {     // tile j = 2kp+half
                int j = 2 * kp + half;
                #pragma unroll
                for (int rr = 0; rr < 2; rr++) {       // rows g / g+8
                    float p0 = sacc[j][rr * 2 + 0];
                    float p1 = sacc[j][rr * 2 + 1];
                    __nv_bfloat16 h0 = __float2bfloat16(p0);
                    __nv_bfloat16 h1 = __float2bfloat16(p1);
                    pha[kp][half * 2 + rr] = pack_bf16x2(h0, h1);
                    pla[kp][half * 2 + rr] = pack_bf16x2(
                        __float2bfloat16(p0 - __bfloat162float(h0)),
                        __float2bfloat16(p1 - __bfloat162float(h1)));
                }
            }
        }
        // reorder: A frag = {a0=(g,klo), a1=(g+8,klo), a2=(g,khi), a3=(g+8,khi)}
        // pha[kp] currently = {j0_row0, j0_row1, j1_row0, j1_row1} == {a0,a1,a2,a3} ✓

        // ---- O += P V (3-term split) ----
        #pragma unroll
        for (int kp = 0; kp < 4; kp++) {
            #pragma unroll
            for (int nb = 0; nb < 8; nb++) {
                uint32_t rh[4], rl[4];
                uint32_t va = stg + 32768 + (kp >> 1) * 8192 +
                              tile_off(nb * 16 + b_rowbase, (uint32_t)((kp & 1) * 2 + b_kadd));
                LDSM4(rh, va);
                LDSM4(rl, va + 16384);
                uint32_t bh0[2] = {rh[0], rh[1]}, bh1[2] = {rh[2], rh[3]};
                uint32_t bl0[2] = {rl[0], rl[1]}, bl1[2] = {rl[2], rl[3]};
                MMA16816(oacc[nb*2],   pha[kp], bh0);
                MMA16816(oacc[nb*2],   pha[kp], bl0);
                MMA16816(oacc[nb*2],   pla[kp], bh0);
                MMA16816(oacc[nb*2+1], pha[kp], bh1);
                MMA16816(oacc[nb*2+1], pha[kp], bl1);
                MMA16816(oacc[nb*2+1], pla[kp], bh1);
            }
        }
        __syncthreads();
    }

    // ---- epilogue ----
    float inv0 = 1.0f / l0, inv1 = 1.0f / l1;
    int r0 = q0 + wm0 + g, r1 = r0 + 8;
    #pragma unroll
    for (int nt = 0; nt < 16; nt++) {
        int col = h * HDIM + nt * 8 + t4 * 2;
        *(float2*)(Y + (size_t)(b * SEQ + r0) * EMB + col) =
            make_float2(oacc[nt][0] * inv0, oacc[nt][1] * inv0);
        *(float2*)(Y + (size_t)(b * SEQ + r1) * EMB + col) =
            make_float2(oacc[nt][2] * inv1, oacc[nt][3] * inv1);
    }
}

// ---------------------------------------------------------------------------
// Launch
// ---------------------------------------------------------------------------
extern "C" void kernel_launch(void* const* d_in, const int* in_sizes, int n_in,
                              void* d_out, int out_size) {
    const float* x  = (const float*)d_in[0];
    const float* wq = (const float*)d_in[1];
    const float* wk = (const float*)d_in[2];
    const float* wv = (const float*)d_in[3];
    const float* wo = (const float*)d_in[4];
    float* out = (float*)d_out;

    float *qp, *kp, *vp, *yp, *cp, *sp;
    __nv_bfloat16 *ahi, *alo, *whi, *wlo, *qhi, *qlo, *khi, *klo, *vthi, *vtlo;
    cudaGetSymbolAddress((void**)&qp, g_Q);
    cudaGetSymbolAddress((void**)&kp, g_K);
    cudaGetSymbolAddress((void**)&vp, g_V);
    cudaGetSymbolAddress((void**)&yp, g_Y);
    cudaGetSymbolAddress((void**)&cp, g_cos);
    cudaGetSymbolAddress((void**)&sp, g_sin);
    cudaGetSymbolAddress((void**)&ahi, g_Ahi);
    cudaGetSymbolAddress((void**)&alo, g_Alo);
    cudaGetSymbolAddress((void**)&whi, g_Whi);
    cudaGetSymbolAddress((void**)&wlo, g_Wlo);
    cudaGetSymbolAddress((void**)&qhi, g_Qhi);
    cudaGetSymbolAddress((void**)&qlo, g_Qlo);
    cudaGetSymbolAddress((void**)&khi, g_Khi);
    cudaGetSymbolAddress((void**)&klo, g_Klo);
    cudaGetSymbolAddress((void**)&vthi, g_Vthi);
    cudaGetSymbolAddress((void**)&vtlo, g_Vtlo);

    cudaFuncSetAttribute(tc_gemm, cudaFuncAttributeMaxDynamicSharedMemorySize,
                         GEMM_SMEM_BYTES);
    cudaFuncSetAttribute(attn_mma, cudaFuncAttributeMaxDynamicSharedMemorySize,
                         ATTN_SMEM_BYTES);

    rope_table_kernel<<<(SEQ * (HDIM/2) + 255) / 256, 256>>>(cp, sp);

    int n4 = MTOT * GK / 4;
    split_bf16_kernel<<<(n4 + 255) / 256, 256>>>(x, ahi, alo, n4);

    dim3 tg(32, 8);
    dim3 tgrid(GN / 32, GK / 32);
    dim3 gg(GN / 128, MTOT / 128);

    transpose_split_kernel<<<tgrid, tg>>>(wq, whi, wlo);
    tc_gemm<<<gg, 256, GEMM_SMEM_BYTES>>>(ahi, alo, whi, wlo, qp);
    transpose_split_kernel<<<tgrid, tg>>>(wk, whi, wlo);
    tc_gemm<<<gg, 256, GEMM_SMEM_BYTES>>>(ahi, alo, whi, wlo, kp);
    transpose_split_kernel<<<tgrid, tg>>>(wv, whi, wlo);
    tc_gemm<<<gg, 256, GEMM_SMEM_BYTES>>>(ahi, alo, whi, wlo, vp);

    // RoPE + split Q,K -> bf16 hi/lo
    int rope_threads = MTOT * NHEAD * (HDIM/2);
    rope_split_kernel<<<(rope_threads + 255) / 256, 256>>>(
        qp, kp, cp, sp, qhi, qlo, khi, klo);

    // V transpose + split -> [b,h,d,s]
    dim3 vtg(SEQ / 32, HDIM / 32, BATCH * NHEAD);
    vtrans_split_kernel<<<vtg, tg>>>(vp, vthi, vtlo);

    // Tensor-core flash attention
    dim3 ag(SEQ / 128, NHEAD, BATCH);  // (16, 16, 2)
    attn_mma<<<ag, 256, ATTN_SMEM_BYTES>>>(qhi, qlo, khi, klo, vthi, vtlo, yp);

    // out = y @ wo
    split_bf16_kernel<<<(n4 + 255) / 256, 256>>>(yp, ahi, alo, n4);
    transpose_split_kernel<<<tgrid, tg>>>(wo, whi, wlo);
    tc_gemm<<<gg, 256, GEMM_SMEM_BYTES>>>(ahi, alo, whi, wlo, out);
}

// round 13
// speedup vs baseline: 3.0307x; 1.0113x over previous
#include <cuda_runtime.h>
#include <cuda_bf16.h>
#include <math.h>
#include <stdint.h>

// Problem constants
#define BATCH   2
#define SEQ     2048
#define EMB     2048
#define NHEAD   16
#define HDIM    128
#define MTOT    (BATCH*SEQ)          // 4096
#define GK      2048
#define GN      2048
#define ATT_SCALE 0.08838834764831845f  // 1/sqrt(128)

// Scratch (device globals: allocation-free)
__device__ float g_cos[SEQ*(HDIM/2)];
__device__ float g_sin[SEQ*(HDIM/2)];
__device__ __nv_bfloat16 g_Ahi[MTOT*GK];
__device__ __nv_bfloat16 g_Alo[MTOT*GK];
__device__ __nv_bfloat16 g_Whi[4*GN*GK];   // wq,wk,wv,wo in [K,N], hi
__device__ __nv_bfloat16 g_Wlo[4*GN*GK];   // lo
__device__ __nv_bfloat16 g_Qhi[MTOT*EMB];
__device__ __nv_bfloat16 g_Qlo[MTOT*EMB];
__device__ __nv_bfloat16 g_Khi[MTOT*EMB];
__device__ __nv_bfloat16 g_Klo[MTOT*EMB];
__device__ __nv_bfloat16 g_Vhi[MTOT*EMB];  // [b,s,h,d]
__device__ __nv_bfloat16 g_Vlo[MTOT*EMB];
__device__ __nv_bfloat16 g_Yhi[MTOT*EMB];
__device__ __nv_bfloat16 g_Ylo[MTOT*EMB];

// ============================================================================
// PTX helpers (portable sm_80+ only)
// ============================================================================
__device__ __forceinline__ uint32_t smem_u32(const void* p) {
    uint32_t a;
    asm("{ .reg .u64 t; cvta.to.shared.u64 t, %1; cvt.u32.u64 %0, t; }"
        : "=r"(a) : "l"(p));
    return a;
}

#define CP_ASYNC16(dst, src) \
    asm volatile("cp.async.cg.shared.global [%0], [%1], 16;" \
                 :: "r"(dst), "l"(src) : "memory")
#define CP_COMMIT() asm volatile("cp.async.commit_group;" ::: "memory")
#define CP_WAIT1()  asm volatile("cp.async.wait_group 1;" ::: "memory")
#define CP_WAIT0()  asm volatile("cp.async.wait_group 0;" ::: "memory")

#define LDSM4(r, addr)                                                         \
    asm volatile("ldmatrix.sync.aligned.m8n8.x4.shared.b16 {%0,%1,%2,%3}, [%4];" \
                 : "=r"((r)[0]), "=r"((r)[1]), "=r"((r)[2]), "=r"((r)[3])      \
                 : "r"(addr))

#define LDSM4T(r, addr)                                                        \
    asm volatile("ldmatrix.sync.aligned.m8n8.x4.trans.shared.b16 {%0,%1,%2,%3}, [%4];" \
                 : "=r"((r)[0]), "=r"((r)[1]), "=r"((r)[2]), "=r"((r)[3])      \
                 : "r"(addr))

#define MMA16816(d, a, b)                                                      \
    asm volatile(                                                              \
        "mma.sync.aligned.m16n8k16.row.col.f32.bf16.bf16.f32 "                 \
        "{%0,%1,%2,%3}, {%4,%5,%6,%7}, {%8,%9}, {%0,%1,%2,%3};"                \
        : "+f"((d)[0]), "+f"((d)[1]), "+f"((d)[2]), "+f"((d)[3])               \
        : "r"((a)[0]), "r"((a)[1]), "r"((a)[2]), "r"((a)[3]),                  \
          "r"((b)[0]), "r"((b)[1]))

__device__ __forceinline__ uint32_t pack_bf16x2(__nv_bfloat16 x, __nv_bfloat16 y) {
    __nv_bfloat162 v(x, y);
    return *reinterpret_cast<uint32_t*>(&v);
}

// A tile: [rows][64B], 4 slots of 16B, swizzle period-8
__device__ __forceinline__ uint32_t tile_off(uint32_t row, uint32_t slot) {
    return row * 64 + ((slot ^ ((row >> 1) & 3)) << 4);
}
// B tile: [rows][256B], 16 slots of 16B, swizzle period-8
__device__ __forceinline__ uint32_t btile_off(uint32_t row, uint32_t slot) {
    return row * 256 + ((slot ^ (row & 7)) << 4);
}

__device__ __forceinline__ void split1(float v, __nv_bfloat16& h, __nv_bfloat16& l) {
    h = __float2bfloat16(v);
    l = __float2bfloat16(v - __bfloat162float(h));
}

// ============================================================================
// Fused split: z=0 -> x (2M float4), z=1..4 -> weights (1M float4 each, [K,N])
// ============================================================================
__global__ void split_multi(const float* __restrict__ x,
                            const float* __restrict__ wq, const float* __restrict__ wk,
                            const float* __restrict__ wv, const float* __restrict__ wo,
                            __nv_bfloat16* __restrict__ ahi, __nv_bfloat16* __restrict__ alo,
                            __nv_bfloat16* __restrict__ whi, __nv_bfloat16* __restrict__ wlo) {
    int z = blockIdx.z;
    const float* src;
    __nv_bfloat16 *dh, *dl;
    int n4;
    if (z == 0) { src = x; dh = ahi; dl = alo; n4 = MTOT * GK / 4; }
    else {
        src = (z == 1) ? wq : (z == 2) ? wk : (z == 3) ? wv : wo;
        dh = whi + (size_t)(z - 1) * GN * GK;
        dl = wlo + (size_t)(z - 1) * GN * GK;
        n4 = GN * GK / 4;
    }
    int i = blockIdx.x * blockDim.x + threadIdx.x;
    if (i >= n4) return;
    float4 v = ((const float4*)src)[i];
    __nv_bfloat16 h0, h1, h2, h3, l0, l1, l2, l3;
    split1(v.x, h0, l0); split1(v.y, h1, l1);
    split1(v.z, h2, l2); split1(v.w, h3, l3);
    __nv_bfloat162* hp = (__nv_bfloat162*)dh;
    __nv_bfloat162* lp = (__nv_bfloat162*)dl;
    hp[i*2+0] = __nv_bfloat162(h0, h1);
    hp[i*2+1] = __nv_bfloat162(h2, h3);
    lp[i*2+0] = __nv_bfloat162(l0, l1);
    lp[i*2+1] = __nv_bfloat162(l2, l3);
}

// ---------------------------------------------------------------------------
// RoPE table
// ---------------------------------------------------------------------------
__global__ void rope_table_kernel(float* ct, float* st) {
    int idx = blockIdx.x * blockDim.x + threadIdx.x;
    if (idx >= SEQ * (HDIM/2)) return;
    int s = idx >> 6;
    int j = idx & 63;
    float inv = powf(10000.0f, -((float)(2*j)) / 128.0f);
    float a = (float)s * inv;
    ct[idx] = cosf(a);
    st[idx] = sinf(a);
}

// ============================================================================
// Shared GEMM mainloop: acc = A[M,K] * W[K,N] (split-bf16, 3 terms)
// A hi/lo [M,K] (k contiguous); B hi/lo [K,N] (n contiguous, ldmatrix.trans).
// 128x128 CTA tile, BK=32, 8 warps (2x4), 3-stage cp.async pipeline.
// Stage layout (32KB): Ahi@0, Alo@8192, Bhi@16384, Blo@24576
// ============================================================================
#define NKB (GK / 32)
#define G_STAGE 32768
#define GEMM_SMEM_BYTES (3*G_STAGE)

__device__ __forceinline__ void gemm_mainloop(
    const __nv_bfloat16* __restrict__ Ahi, const __nv_bfloat16* __restrict__ Alo,
    const __nv_bfloat16* __restrict__ Bhi, const __nv_bfloat16* __restrict__ Blo,
    uint32_t base, int tid, int m0, int n0, float (&acc)[4][4][4]) {
    const int wid  = tid >> 5;
    const int lane = tid & 31;
    const int wm = wid >> 2;
    const int wn = wid & 3;

    #pragma unroll
    for (int mt = 0; mt < 4; mt++)
        #pragma unroll
        for (int nt = 0; nt < 4; nt++)
            #pragma unroll
            for (int e = 0; e < 4; e++) acc[mt][nt][e] = 0.0f;

    const uint32_t a_row  = wm * 64 + (lane & 15);
    const int      a_kadd = lane >> 4;
    const uint32_t b_row16 = lane & 15;        // k-row within 16-group
    const uint32_t b_sadd  = lane >> 4;        // n16 sub-slot

    auto issue = [&](int kb) {
        const int kcol = kb * 32;
        const uint32_t stg = base + (kb % 3) * G_STAGE;
        #pragma unroll
        for (int i = 0; i < 2; i++) {
            int c = i * 256 + tid;               // 0..511
            {   // A: row 0..127, slot 0..3
                uint32_t row = c >> 2, slot = c & 3;
                const __nv_bfloat16* s = Ahi + (size_t)(m0 + row) * GK + kcol + slot * 8;
                const __nv_bfloat16* s2 = Alo + (size_t)(m0 + row) * GK + kcol + slot * 8;
                uint32_t d = stg + tile_off(row, slot);
                CP_ASYNC16(d, s);
                CP_ASYNC16(d + 8192, s2);
            }
            {   // B: row 0..31 (k), slot 0..15 (n16)
                uint32_t row = c >> 4, slot = c & 15;
                const __nv_bfloat16* s = Bhi + (size_t)(kcol + row) * GN + n0 + slot * 8;
                const __nv_bfloat16* s2 = Blo + (size_t)(kcol + row) * GN + n0 + slot * 8;
                uint32_t d = stg + 16384 + btile_off(row, slot);
                CP_ASYNC16(d, s);
                CP_ASYNC16(d + 8192, s2);
            }
        }
        CP_COMMIT();
    };

    issue(0);
    issue(1);

    for (int kb = 0; kb < NKB; kb++) {
        if (kb < NKB - 1) CP_WAIT1(); else CP_WAIT0();
        __syncthreads();
        if (kb + 2 < NKB) issue(kb + 2);

        const uint32_t st = base + (kb % 3) * G_STAGE;

        #pragma unroll
        for (int ks = 0; ks < 2; ks++) {
            uint32_t ahi[4][4], alo[4][4], bhi[4][2], blo[4][2];
            #pragma unroll
            for (int mt = 0; mt < 4; mt++) {
                uint32_t row = a_row + mt * 16;
                uint32_t ad  = st + tile_off(row, (uint32_t)(ks * 2 + a_kadd));
                LDSM4(ahi[mt], ad);
                LDSM4(alo[mt], ad + 8192);
            }
            #pragma unroll
            for (int np = 0; np < 2; np++) {
                uint32_t row = ks * 16 + b_row16;
                uint32_t slot = wn * 4 + np * 2 + b_sadd;
                uint32_t bd = st + 16384 + btile_off(row, slot);
                uint32_t r[4];
                LDSM4T(r, bd);
                bhi[np*2][0] = r[0]; bhi[np*2][1] = r[1];
                bhi[np*2+1][0] = r[2]; bhi[np*2+1][1] = r[3];
                LDSM4T(r, bd + 8192);
                blo[np*2][0] = r[0]; blo[np*2][1] = r[1];
                blo[np*2+1][0] = r[2]; blo[np*2+1][1] = r[3];
            }
            #pragma unroll
            for (int mt = 0; mt < 4; mt++)
                #pragma unroll
                for (int nt = 0; nt < 4; nt++) {
                    MMA16816(acc[mt][nt], ahi[mt], bhi[nt]);
                    MMA16816(acc[mt][nt], ahi[mt], blo[nt]);
                    MMA16816(acc[mt][nt], alo[mt], bhi[nt]);
                }
        }
    }
}

// ---- QKV GEMM: z=0 Q(rope), z=1 K(rope), z=2 V(plain split) ----
__global__ __launch_bounds__(256) void qkv_gemm(
    const __nv_bfloat16* __restrict__ Ahi, const __nv_bfloat16* __restrict__ Alo,
    const __nv_bfloat16* __restrict__ Whi, const __nv_bfloat16* __restrict__ Wlo,
    const float* __restrict__ ct, const float* __restrict__ st,
    __nv_bfloat16* __restrict__ Qhi, __nv_bfloat16* __restrict__ Qlo,
    __nv_bfloat16* __restrict__ Khi, __nv_bfloat16* __restrict__ Klo,
    __nv_bfloat16* __restrict__ Vhi, __nv_bfloat16* __restrict__ Vlo) {
    extern __shared__ char smraw[];
    const uint32_t base = smem_u32(smraw);
    const int tid = threadIdx.x;
    const int m0 = blockIdx.y * 128;
    const int n0 = blockIdx.x * 128;
    const int z  = blockIdx.z;
    const __nv_bfloat16* Bh = Whi + (size_t)z * GN * GK;
    const __nv_bfloat16* Bl = Wlo + (size_t)z * GN * GK;

    float acc[4][4][4];
    gemm_mainloop(Ahi, Alo, Bh, Bl, base, tid, m0, n0, acc);

    const int wid = tid >> 5, lane = tid & 31;
    const int wm = wid >> 2, wn = wid & 3;
    const int r0 = m0 + wm * 64 + (lane >> 2);
    const int c0 = n0 + wn * 32 + (lane & 3) * 2;
    __nv_bfloat16* Hi = (z == 0) ? Qhi : (z == 1) ? Khi : Vhi;
    __nv_bfloat16* Lo = (z == 0) ? Qlo : (z == 1) ? Klo : Vlo;
    const bool dorope = (z < 2);

    #pragma unroll
    for (int mt = 0; mt < 4; mt++)
        #pragma unroll
        for (int nt = 0; nt < 4; nt++) {
            int col = c0 + nt * 8;
            int j = (col & 127) >> 1;
            #pragma unroll
            for (int rr = 0; rr < 2; rr++) {
                int row = r0 + mt * 16 + rr * 8;
                float x1 = acc[mt][nt][rr*2], x2 = acc[mt][nt][rr*2+1];
                if (dorope) {
                    int s = row & (SEQ - 1);
                    float cv = ct[(s << 6) + j], sv = st[(s << 6) + j];
                    float n1 = x1 * cv - x2 * sv;
                    float n2 = x1 * sv + x2 * cv;
                    x1 = n1; x2 = n2;
                }
                __nv_bfloat16 h1, h2, l1, l2;
                split1(x1, h1, l1); split1(x2, h2, l2);
                size_t o = (size_t)row * EMB + col;
                *(uint32_t*)(Hi + o) = pack_bf16x2(h1, h2);
                *(uint32_t*)(Lo + o) = pack_bf16x2(l1, l2);
            }
        }
}

// ---- Output GEMM: fp32 epilogue ----
__global__ __launch_bounds__(256) void out_gemm(
    const __nv_bfloat16* __restrict__ Ahi, const __nv_bfloat16* __restrict__ Alo,
    const __nv_bfloat16* __restrict__ Bhi, const __nv_bfloat16* __restrict__ Blo,
    float* __restrict__ C) {
    extern __shared__ char smraw[];
    const uint32_t base = smem_u32(smraw);
    const int tid = threadIdx.x;
    const int m0 = blockIdx.y * 128;
    const int n0 = blockIdx.x * 128;

    float acc[4][4][4];
    gemm_mainloop(Ahi, Alo, Bhi, Blo, base, tid, m0, n0, acc);

    const int wid = tid >> 5, lane = tid & 31;
    const int wm = wid >> 2, wn = wid & 3;
    const int r0  = m0 + wm * 64 + (lane >> 2);
    const int col = n0 + wn * 32 + (lane & 3) * 2;
    #pragma unroll
    for (int mt = 0; mt < 4; mt++)
        #pragma unroll
        for (int nt = 0; nt < 4; nt++) {
            float* d = acc[mt][nt];
            size_t o0 = (size_t)(r0 + mt * 16)     * GN + col + nt * 8;
            size_t o1 = (size_t)(r0 + mt * 16 + 8) * GN + col + nt * 8;
            *(float2*)(C + o0) = make_float2(d[0], d[1]);
            *(float2*)(C + o1) = make_float2(d[2], d[3]);
        }
}

// ============================================================================
// Tensor-core causal flash attention (split-bf16, 3-term).
// BQ=128 (8 warps x m16), BK=64, cp.async double-buffered K/V, Q resident.
// smem: Qhi/Qlo [4 chunks][128x32] @ 0/32768;
//       stage s @ 65536+s*65536: Khi(16K) Klo(16K) Vhi(16K) Vlo(16K)
// V stored [64 s][256B d] with btile swizzle, consumed via ldmatrix.trans.
// Epilogue writes Yhi/Ylo bf16 split.
// ============================================================================
#define ATTN_Q_BYTES     65536
#define ATTN_STAGE_BYTES 65536
#define ATTN_SMEM_BYTES  (ATTN_Q_BYTES + 2*ATTN_STAGE_BYTES)  // 196608

__global__ __launch_bounds__(256, 1) void attn_mma(
    const __nv_bfloat16* __restrict__ Qhi, const __nv_bfloat16* __restrict__ Qlo,
    const __nv_bfloat16* __restrict__ Khi, const __nv_bfloat16* __restrict__ Klo,
    const __nv_bfloat16* __restrict__ Vhi, const __nv_bfloat16* __restrict__ Vlo,
    __nv_bfloat16* __restrict__ Yhi, __nv_bfloat16* __restrict__ Ylo) {
    extern __shared__ char smraw[];
    const uint32_t base = smem_u32(smraw);
    const int tid = threadIdx.x, wid = tid >> 5, lane = tid & 31;
    const int qb = blockIdx.x, h = blockIdx.y, b = blockIdx.z;
    const int q0 = qb * 128;
    const int wm0 = wid * 16;
    const int g = lane >> 2, t4 = lane & 3;
    const int ntiles = 2 * qb + 2;

    const uint32_t a_row = wm0 + (lane & 15);
    const int a_kadd = lane >> 4;
    const uint32_t b_rowbase = (lane & 7) + ((lane & 16) >> 1);
    const int b_kadd = (lane >> 3) & 1;
    const uint32_t v_row16 = lane & 15;
    const uint32_t v_sadd  = lane >> 4;

    // Q load (grouped with stage 0's commit)
    #pragma unroll
    for (int i = 0; i < 8; i++) {
        int c = i * 256 + tid;
        uint32_t row = (c >> 2) & 127, slot = c & 3, kc = c >> 9;
        size_t src = ((size_t)(b * SEQ + q0 + row)) * EMB + h * HDIM + kc * 32 + slot * 8;
        uint32_t dst = base + kc * 8192 + tile_off(row, slot);
        CP_ASYNC16(dst, Qhi + src);
        CP_ASYNC16(dst + 32768, Qlo + src);
    }

    auto issueKV = [&](int kt) {
        const int k0 = kt * 64;
        const uint32_t stg = base + ATTN_Q_BYTES + (kt & 1) * ATTN_STAGE_BYTES;
        #pragma unroll
        for (int i = 0; i < 4; i++) {
            int c = i * 256 + tid;
            {   // K tile: [64 rows][128 cols] -> 4 chunks of [64][32]
                uint32_t row = (c >> 2) & 63, slot = c & 3, kc = c >> 8;
                size_t src = ((size_t)(b * SEQ + k0 + row)) * EMB + h * HDIM + kc * 32 + slot * 8;
                uint32_t dst = stg + kc * 4096 + tile_off(row, slot);
                CP_ASYNC16(dst, Khi + src);
                CP_ASYNC16(dst + 16384, Klo + src);
            }
            {   // V tile: [64 s][256B d], btile swizzle
                uint32_t row = c >> 4, slot = c & 15;
                size_t src = ((size_t)(b * SEQ + k0 + row)) * EMB + h * HDIM + slot * 8;
                uint32_t dst = stg + 32768 + btile_off(row, slot);
                CP_ASYNC16(dst, Vhi + src);
                CP_ASYNC16(dst + 16384, Vlo + src);
            }
        }
        CP_COMMIT();
    };

    issueKV(0);

    float oacc[16][4];
    #pragma unroll
    for (int nt = 0; nt < 16; nt++)
        #pragma unroll
        for (int e = 0; e < 4; e++) oacc[nt][e] = 0.0f;
    float m0 = -1e30f, m1 = -1e30f, l0 = 0.0f, l1 = 0.0f;

    const int r0g = q0 + wm0 + g;

    for (int kt = 0; kt < ntiles; kt++) {
        if (kt + 1 < ntiles) { issueKV(kt + 1); CP_WAIT1(); }
        else                 { CP_WAIT0(); }
        __syncthreads();

        const int k0 = kt * 64;
        const uint32_t stg = base + ATTN_Q_BYTES + (kt & 1) * ATTN_STAGE_BYTES;

        // ---- S = Q K^T (3-term split) ----
        float sacc[8][4];
        #pragma unroll
        for (int nt = 0; nt < 8; nt++)
            #pragma unroll
            for (int e = 0; e < 4; e++) sacc[nt][e] = 0.0f;

        #pragma unroll
        for (int ks = 0; ks < 8; ks++) {
            uint32_t ah[4], al[4];
            uint32_t qa = base + (ks >> 1) * 8192 +
                          tile_off(a_row, (uint32_t)((ks & 1) * 2 + a_kadd));
            LDSM4(ah, qa);
            LDSM4(al, qa + 32768);
            #pragma unroll
            for (int np = 0; np < 4; np++) {
                uint32_t rh[4], rl[4];
                uint32_t ka = stg + (ks >> 1) * 4096 +
                              tile_off(np * 16 + b_rowbase, (uint32_t)((ks & 1) * 2 + b_kadd));
                LDSM4(rh, ka);
                LDSM4(rl, ka + 16384);
                uint32_t bh0[2] = {rh[0], rh[1]}, bh1[2] = {rh[2], rh[3]};
                uint32_t bl0[2] = {rl[0], rl[1]}, bl1[2] = {rl[2], rl[3]};
                MMA16816(sacc[np*2],   ah, bh0);
                MMA16816(sacc[np*2],   ah, bl0);
                MMA16816(sacc[np*2],   al, bh0);
                MMA16816(sacc[np*2+1], ah, bh1);
                MMA16816(sacc[np*2+1], ah, bl1);
                MMA16816(sacc[np*2+1], al, bh1);
            }
        }

        // ---- scale + causal mask ----
        #pragma unroll
        for (int nt = 0; nt < 8; nt++)
            #pragma unroll
            for (int e = 0; e < 4; e++) sacc[nt][e] *= ATT_SCALE;

        if (k0 + 63 > q0 + wm0) {
            #pragma unroll
            for (int nt = 0; nt < 8; nt++) {
                int c0 = k0 + nt * 8 + t4 * 2;
                if (c0     > r0g)     sacc[nt][0] = -1e30f;
                if (c0 + 1 > r0g)     sacc[nt][1] = -1e30f;
                if (c0     > r0g + 8) sacc[nt][2] = -1e30f;
                if (c0 + 1 > r0g + 8) sacc[nt][3] = -1e30f;
            }
        }

        // ---- online softmax (rows g and g+8) ----
        float mx0 = -1e30f, mx1 = -1e30f;
        #pragma unroll
        for (int nt = 0; nt < 8; nt++) {
            mx0 = fmaxf(mx0, fmaxf(sacc[nt][0], sacc[nt][1]));
            mx1 = fmaxf(mx1, fmaxf(sacc[nt][2], sacc[nt][3]));
        }
        mx0 = fmaxf(mx0, __shfl_xor_sync(0xffffffffu, mx0, 1));
        mx0 = fmaxf(mx0, __shfl_xor_sync(0xffffffffu, mx0, 2));
        mx1 = fmaxf(mx1, __shfl_xor_sync(0xffffffffu, mx1, 1));
        mx1 = fmaxf(mx1, __shfl_xor_sync(0xffffffffu, mx1, 2));
        float mn0 = fmaxf(m0, mx0), mn1 = fmaxf(m1, mx1);
        float sf0 = __expf(m0 - mn0), sf1 = __expf(m1 - mn1);
        m0 = mn0; m1 = mn1;
        float sum0 = 0.0f, sum1 = 0.0f;
        #pragma unroll
        for (int nt = 0; nt < 8; nt++) {
            sacc[nt][0] = __expf(sacc[nt][0] - mn0); sum0 += sacc[nt][0];
            sacc[nt][1] = __expf(sacc[nt][1] - mn0); sum0 += sacc[nt][1];
            sacc[nt][2] = __expf(sacc[nt][2] - mn1); sum1 += sacc[nt][2];
            sacc[nt][3] = __expf(sacc[nt][3] - mn1); sum1 += sacc[nt][3];
        }
        sum0 += __shfl_xor_sync(0xffffffffu, sum0, 1);
        sum0 += __shfl_xor_sync(0xffffffffu, sum0, 2);
        sum1 += __shfl_xor_sync(0xffffffffu, sum1, 1);
        sum1 += __shfl_xor_sync(0xffffffffu, sum1, 2);
        l0 = l0 * sf0 + sum0;
        l1 = l1 * sf1 + sum1;
        #pragma unroll
        for (int nt = 0; nt < 16; nt++) {
            oacc[nt][0] *= sf0; oacc[nt][1] *= sf0;
            oacc[nt][2] *= sf1; oacc[nt][3] *= sf1;
        }

        // ---- P fragments (acc -> A operand, hi/lo split, in-register) ----
        uint32_t pha[4][4], pla[4][4];
        #pragma unroll
        for (int kp = 0; kp < 4; kp++) {
            #pragma unroll
            for (int half = 0; half < 2; half++) {
                int j = 2 * kp + half;
                #pragma unroll
                for (int rr = 0; rr < 2; rr++) {
                    float p0 = sacc[j][rr * 2 + 0];
                    float p1 = sacc[j][rr * 2 + 1];
                    __nv_bfloat16 h0 = __float2bfloat16(p0);
                    __nv_bfloat16 h1 = __float2bfloat16(p1);
                    pha[kp][half * 2 + rr] = pack_bf16x2(h0, h1);
                    pla[kp][half * 2 + rr] = pack_bf16x2(
                        __float2bfloat16(p0 - __bfloat162float(h0)),
                        __float2bfloat16(p1 - __bfloat162float(h1)));
                }
            }
        }

        // ---- O += P V (3-term split); V via ldmatrix.trans ----
        #pragma unroll
        for (int kp = 0; kp < 4; kp++) {
            uint32_t vrow = kp * 16 + v_row16;
            #pragma unroll
            for (int nb = 0; nb < 8; nb++) {
                uint32_t rh[4], rl[4];
                uint32_t va = stg + 32768 + btile_off(vrow, nb * 2 + v_sadd);
                LDSM4T(rh, va);
                LDSM4T(rl, va + 16384);
                uint32_t bh0[2] = {rh[0], rh[1]}, bh1[2] = {rh[2], rh[3]};
                uint32_t bl0[2] = {rl[0], rl[1]}, bl1[2] = {rl[2], rl[3]};
                MMA16816(oacc[nb*2],   pha[kp], bh0);
                MMA16816(oacc[nb*2],   pha[kp], bl0);
                MMA16816(oacc[nb*2],   pla[kp], bh0);
                MMA16816(oacc[nb*2+1], pha[kp], bh1);
                MMA16816(oacc[nb*2+1], pha[kp], bl1);
                MMA16816(oacc[nb*2+1], pla[kp], bh1);
            }
        }
        __syncthreads();
    }

    // ---- epilogue: write Yhi/Ylo bf16 split ----
    float inv0 = 1.0f / l0, inv1 = 1.0f / l1;
    int r0 = q0 + wm0 + g, r1 = r0 + 8;
    #pragma unroll
    for (int nt = 0; nt < 16; nt++) {
        int col = h * HDIM + nt * 8 + t4 * 2;
        size_t o0 = (size_t)(b * SEQ + r0) * EMB + col;
        size_t o1 = (size_t)(b * SEQ + r1) * EMB + col;
        __nv_bfloat16 h0, h1, l0b, l1b;
        split1(oacc[nt][0] * inv0, h0, l0b);
        split1(oacc[nt][1] * inv0, h1, l1b);
        *(uint32_t*)(Yhi + o0) = pack_bf16x2(h0, h1);
        *(uint32_t*)(Ylo + o0) = pack_bf16x2(l0b, l1b);
        split1(oacc[nt][2] * inv1, h0, l0b);
        split1(oacc[nt][3] * inv1, h1, l1b);
        *(uint32_t*)(Yhi + o1) = pack_bf16x2(h0, h1);
        *(uint32_t*)(Ylo + o1) = pack_bf16x2(l0b, l1b);
    }
}

// ---------------------------------------------------------------------------
// Launch
// ---------------------------------------------------------------------------
extern "C" void kernel_launch(void* const* d_in, const int* in_sizes, int n_in,
                              void* d_out, int out_size) {
    const float* x  = (const float*)d_in[0];
    const float* wq = (const float*)d_in[1];
    const float* wk = (const float*)d_in[2];
    const float* wv = (const float*)d_in[3];
    const float* wo = (const float*)d_in[4];
    float* out = (float*)d_out;

    float *cp, *sp;
    __nv_bfloat16 *ahi, *alo, *whi, *wlo;
    __nv_bfloat16 *qhi, *qlo, *khi, *klo, *vhi, *vlo, *yhi, *ylo;
    cudaGetSymbolAddress((void**)&cp, g_cos);
    cudaGetSymbolAddress((void**)&sp, g_sin);
    cudaGetSymbolAddress((void**)&ahi, g_Ahi);
    cudaGetSymbolAddress((void**)&alo, g_Alo);
    cudaGetSymbolAddress((void**)&whi, g_Whi);
    cudaGetSymbolAddress((void**)&wlo, g_Wlo);
    cudaGetSymbolAddress((void**)&qhi, g_Qhi);
    cudaGetSymbolAddress((void**)&qlo, g_Qlo);
    cudaGetSymbolAddress((void**)&khi, g_Khi);
    cudaGetSymbolAddress((void**)&klo, g_Klo);
    cudaGetSymbolAddress((void**)&vhi, g_Vhi);
    cudaGetSymbolAddress((void**)&vlo, g_Vlo);
    cudaGetSymbolAddress((void**)&yhi, g_Yhi);
    cudaGetSymbolAddress((void**)&ylo, g_Ylo);

    cudaFuncSetAttribute(qkv_gemm, cudaFuncAttributeMaxDynamicSharedMemorySize,
                         GEMM_SMEM_BYTES);
    cudaFuncSetAttribute(out_gemm, cudaFuncAttributeMaxDynamicSharedMemorySize,
                         GEMM_SMEM_BYTES);
    cudaFuncSetAttribute(attn_mma, cudaFuncAttributeMaxDynamicSharedMemorySize,
                         ATTN_SMEM_BYTES);

    rope_table_kernel<<<(SEQ * (HDIM/2) + 255) / 256, 256>>>(cp, sp);

    // fused split: x + 4 weights
    {
        int n4max = MTOT * GK / 4;
        dim3 sg((n4max + 255) / 256, 1, 5);
        split_multi<<<sg, 256>>>(x, wq, wk, wv, wo, ahi, alo, whi, wlo);
    }

    // QKV projections + RoPE fused
    dim3 gg(GN / 128, MTOT / 128, 3);
    qkv_gemm<<<gg, 256, GEMM_SMEM_BYTES>>>(ahi, alo, whi, wlo, cp, sp,
                                           qhi, qlo, khi, klo, vhi, vlo);

    // Tensor-core flash attention (writes Yhi/Ylo directly)
    dim3 ag(SEQ / 128, NHEAD, BATCH);
    attn_mma<<<ag, 256, ATTN_SMEM_BYTES>>>(qhi, qlo, khi, klo, vhi, vlo, yhi, ylo);

    // out = y @ wo
    dim3 og(GN / 128, MTOT / 128);
    out_gemm<<<og, 256, GEMM_SMEM_BYTES>>>(yhi, ylo,
                                           whi + (size_t)3 * GN * GK,
                                           wlo + (size_t)3 * GN * GK, out);
}